// round 1
// baseline (speedup 1.0000x reference)
#include <cuda_runtime.h>
#include <cstdint>
#include <math.h>

#define DEVI __device__ __forceinline__

// ---------------- problem constants ----------------
constexpr int CB = 32, CS = 577, CD = 768, CH = 12, CDH = 64, CFF = 3072;
constexpr int MALL = CB * CS;            // 18464 rows
constexpr int SLD  = 580;                // padded leading dim for scores (mult of 4)
constexpr float LNEPS = 1e-5f;

// ---------------- device scratch (allocation-free) ----------------
__device__ float g_h   [MALL * CD];                 // LN1/LN2 output (reused)
__device__ float g_qkv [MALL * 3 * CD];             // [row, 2304] q|k|v (h-major, e)
__device__ float g_sc  [CB * CH * CS * SLD];        // scores/probs, ld=SLD
__device__ float g_ctx [MALL * CD];                 // attention context, concat heads
__device__ float g_x2  [MALL * CD];                 // x + attn_out
__device__ float g_ffn [MALL * CFF];                // GELU(h2 W1 + b1)
__device__ float g_Wqkv[CD * 3 * CD];               // packed+tf32 rounded
__device__ float g_bqkv[3 * CD];
__device__ float g_Wo  [CD * CD];                   // tf32-rounded copies
__device__ float g_W1  [CD * CFF];
__device__ float g_W2  [CFF * CD];

// ---------------- small helpers ----------------
DEVI float tf32r(float x) {
    unsigned u;
    asm("cvt.rna.tf32.f32 %0, %1;" : "=r"(u) : "f"(x));
    return __uint_as_float(u);
}

DEVI float bsum(float v, float* sb) {
    #pragma unroll
    for (int o = 16; o > 0; o >>= 1) v += __shfl_xor_sync(0xffffffffu, v, o);
    __syncthreads();
    if ((threadIdx.x & 31) == 0) sb[threadIdx.x >> 5] = v;
    __syncthreads();
    float t = 0.f;
    #pragma unroll
    for (int i = 0; i < 8; i++) t += sb[i];
    return t;
}

DEVI float bmax(float v, float* sb) {
    #pragma unroll
    for (int o = 16; o > 0; o >>= 1) v = fmaxf(v, __shfl_xor_sync(0xffffffffu, v, o));
    __syncthreads();
    if ((threadIdx.x & 31) == 0) sb[threadIdx.x >> 5] = v;
    __syncthreads();
    float t = -1e30f;
    #pragma unroll
    for (int i = 0; i < 8; i++) t = fmaxf(t, sb[i]);
    return t;
}

// ---------------- pack kernels ----------------
__global__ void pack_qkv_k(const float* __restrict__ Wq, const float* __restrict__ Wk,
                           const float* __restrict__ Wv, const float* __restrict__ bq,
                           const float* __restrict__ bk, const float* __restrict__ bv) {
    int idx = blockIdx.x * 256 + threadIdx.x;
    int total = CD * 3 * CD;
    if (idx < total) {
        int col = idx % (3 * CD), k = idx / (3 * CD);
        int which = col / CD, c = col % CD;
        int h = c >> 6, e = c & 63;
        const float* W = (which == 0) ? Wq : ((which == 1) ? Wk : Wv);
        g_Wqkv[idx] = tf32r(W[(h * CD + k) * CDH + e]);
    }
    if (idx < 3 * CD) {
        int which = idx / CD, c = idx % CD;
        const float* bb = (which == 0) ? bq : ((which == 1) ? bk : bv);
        g_bqkv[idx] = bb[c];
    }
}

__global__ void round_copy_k(float* __restrict__ dst, const float* __restrict__ src, int n) {
    int i = blockIdx.x * 256 + threadIdx.x;
    if (i < n) dst[i] = tf32r(src[i]);
}

// ---------------- layer norm ----------------
__global__ void ln_k(const float* __restrict__ x, const float* __restrict__ w,
                     const float* __restrict__ b, float* __restrict__ o) {
    __shared__ float sb[8];
    long long row = blockIdx.x;
    const float* xr = x + row * CD;
    float v[3];
    float s = 0.f;
    #pragma unroll
    for (int i = 0; i < 3; i++) { v[i] = xr[threadIdx.x + i * 256]; s += v[i]; }
    s = bsum(s, sb);
    float mu = s * (1.f / (float)CD);
    float q = 0.f;
    #pragma unroll
    for (int i = 0; i < 3; i++) { float d = v[i] - mu; q += d * d; }
    q = bsum(q, sb);
    float rs = rsqrtf(q * (1.f / (float)CD) + LNEPS);
    #pragma unroll
    for (int i = 0; i < 3; i++) {
        int c = threadIdx.x + i * 256;
        o[row * CD + c] = tf32r((v[i] - mu) * rs * w[c] + b[c]);
    }
}

// ---------------- softmax (in place, rows of length CS, ld=SLD) ----------------
__global__ void softmax_k(float* __restrict__ p) {
    __shared__ float sb[8];
    float* row = p + (long long)blockIdx.x * SLD;
    float v[3];
    #pragma unroll
    for (int i = 0; i < 3; i++) {
        int idx = threadIdx.x + i * 256;
        v[i] = (idx < CS) ? row[idx] : -1e30f;
    }
    float m = bmax(fmaxf(fmaxf(v[0], v[1]), v[2]), sb);
    float e[3];
    float s = 0.f;
    #pragma unroll
    for (int i = 0; i < 3; i++) {
        int idx = threadIdx.x + i * 256;
        e[i] = (idx < CS) ? expf(v[i] - m) : 0.f;
        s += e[i];
    }
    s = bsum(s, sb);
    float inv = 1.f / s;
    #pragma unroll
    for (int i = 0; i < 3; i++) {
        int idx = threadIdx.x + i * 256;
        if (idx < CS) row[idx] = tf32r(e[i] * inv);
    }
}

// ---------------- tf32 mma GEMM ----------------
// C[M,N] = alpha * A[M,K] (.) B[K,N]  (+bias +gelu/+residual), tf32 mma.sync, fp32 accum.
// TRANSB: B element (k,n) at Bm[n*ldb + k] (both operands k-contiguous).
// Batch: blockIdx.z -> zb = z/batchH, zh = z%batchH; offsets zb*s?b + zh*s?h.
constexpr int BM = 128, BN = 128, BK = 16;
constexpr int LDA_S = BK + 4;    // 20  (conflict-free for A frag loads)
constexpr int LDB_S = BN + 8;    // 136 (conflict-free for B frag loads)

DEVI void cpa16(float* s, const float* g) {
    unsigned a = (unsigned)__cvta_generic_to_shared(s);
    asm volatile("cp.async.cg.shared.global [%0], [%1], 16;" :: "r"(a), "l"(g));
}
DEVI void cpa_commit() { asm volatile("cp.async.commit_group;"); }
template <int N> DEVI void cpa_wait() { asm volatile("cp.async.wait_group %0;" :: "n"(N)); }

DEVI void mma8(float* c, const uint32_t* a, const uint32_t* b) {
    asm volatile(
        "mma.sync.aligned.m16n8k8.row.col.f32.tf32.tf32.f32 "
        "{%0,%1,%2,%3},{%4,%5,%6,%7},{%8,%9},{%0,%1,%2,%3};"
        : "+f"(c[0]), "+f"(c[1]), "+f"(c[2]), "+f"(c[3])
        : "r"(a[0]), "r"(a[1]), "r"(a[2]), "r"(a[3]), "r"(b[0]), "r"(b[1]));
}

template <int EPI, int TRANSB, int RND>
__global__ void __launch_bounds__(256) gemm_k(
    const float* __restrict__ A, const float* __restrict__ Bm,
    float* __restrict__ C, const float* __restrict__ bias,
    const float* __restrict__ res,
    int M, int N, int K, int lda, int ldb, int ldc, float alpha,
    int batchH, long long sAb, long long sAh, long long sBb, long long sBh,
    long long sCb, long long sCh)
{
    __shared__ __align__(16) float As[2][BM * LDA_S];
    __shared__ __align__(16) float Bs[2][BK * LDB_S];

    int z = blockIdx.z;
    int zb = z / batchH, zh = z % batchH;
    A += zb * sAb + zh * sAh;
    Bm += zb * sBb + zh * sBh;
    C += zb * sCb + zh * sCh;
    const float* R = res;
    if (EPI == 3) R = res + zb * sCb + zh * sCh;

    int m0 = blockIdx.y * BM, n0 = blockIdx.x * BN;
    int tid = threadIdx.x;

    auto loadA = [&](int st, int k0) {
        #pragma unroll
        for (int t = 0; t < 2; t++) {
            int v = tid + t * 256;
            int r = v >> 2, cq = (v & 3) << 2;
            int gm = m0 + r, gk = k0 + cq;
            float* dst = &As[st][r * LDA_S + cq];
            if (gm < M && gk + 3 < K) {
                cpa16(dst, A + (long long)gm * lda + gk);
            } else {
                #pragma unroll
                for (int j = 0; j < 4; j++)
                    dst[j] = (gm < M && gk + j < K) ? A[(long long)gm * lda + gk + j] : 0.f;
            }
        }
    };
    auto loadB = [&](int st, int k0) {
        if (!TRANSB) {
            #pragma unroll
            for (int t = 0; t < 2; t++) {
                int v = tid + t * 256;
                int r = v >> 5, cq = (v & 31) << 2;
                int gk = k0 + r, gn = n0 + cq;
                float* dst = &Bs[st][r * LDB_S + cq];
                if (gk < K && gn + 3 < N) {
                    cpa16(dst, Bm + (long long)gk * ldb + gn);
                } else {
                    #pragma unroll
                    for (int j = 0; j < 4; j++)
                        dst[j] = (gk < K && gn + j < N) ? Bm[(long long)gk * ldb + gn + j] : 0.f;
                }
            }
        } else {
            #pragma unroll
            for (int t = 0; t < 2; t++) {
                int v = tid + t * 256;
                int n = v >> 2, kq = (v & 3) << 2;
                int gn = n0 + n, gk = k0 + kq;
                float4 val = make_float4(0.f, 0.f, 0.f, 0.f);
                if (gn < N) {
                    if (gk + 3 < K) {
                        val = *(const float4*)(Bm + (long long)gn * ldb + gk);
                    } else {
                        float* pv = (float*)&val;
                        #pragma unroll
                        for (int j = 0; j < 4; j++)
                            if (gk + j < K) pv[j] = Bm[(long long)gn * ldb + gk + j];
                    }
                }
                Bs[st][(kq + 0) * LDB_S + n] = val.x;
                Bs[st][(kq + 1) * LDB_S + n] = val.y;
                Bs[st][(kq + 2) * LDB_S + n] = val.z;
                Bs[st][(kq + 3) * LDB_S + n] = val.w;
            }
        }
    };

    int lane = tid & 31, wid = tid >> 5;
    int wm = (wid >> 2) * 64;        // 0 or 64
    int wn = (wid & 3) * 32;         // 0,32,64,96
    int g = lane >> 2, tg = lane & 3;

    float acc[4][4][4];
    #pragma unroll
    for (int i = 0; i < 4; i++)
        #pragma unroll
        for (int j = 0; j < 4; j++)
            #pragma unroll
            for (int q = 0; q < 4; q++) acc[i][j][q] = 0.f;

    int nk = (K + BK - 1) / BK;
    loadA(0, 0); loadB(0, 0); cpa_commit();

    for (int kt = 0; kt < nk; ++kt) {
        int st = kt & 1;
        if (kt + 1 < nk) {
            loadA(st ^ 1, (kt + 1) * BK);
            loadB(st ^ 1, (kt + 1) * BK);
            cpa_commit();
            cpa_wait<1>();
        } else {
            cpa_wait<0>();
        }
        __syncthreads();

        #pragma unroll
        for (int kk = 0; kk < BK; kk += 8) {
            uint32_t af[4][4], bf[4][2];
            #pragma unroll
            for (int i = 0; i < 4; i++) {
                int r = wm + i * 16;
                af[i][0] = __float_as_uint(As[st][(r + g    ) * LDA_S + kk + tg    ]);
                af[i][1] = __float_as_uint(As[st][(r + g + 8) * LDA_S + kk + tg    ]);
                af[i][2] = __float_as_uint(As[st][(r + g    ) * LDA_S + kk + tg + 4]);
                af[i][3] = __float_as_uint(As[st][(r + g + 8) * LDA_S + kk + tg + 4]);
            }
            #pragma unroll
            for (int j = 0; j < 4; j++) {
                int c = wn + j * 8 + g;
                bf[j][0] = __float_as_uint(Bs[st][(kk + tg    ) * LDB_S + c]);
                bf[j][1] = __float_as_uint(Bs[st][(kk + tg + 4) * LDB_S + c]);
            }
            #pragma unroll
            for (int i = 0; i < 4; i++)
                #pragma unroll
                for (int j = 0; j < 4; j++) mma8(acc[i][j], af[i], bf[j]);
        }
        __syncthreads();
    }

    auto emit = [&](int r, int c, float v) {
        if (r < M && c < N) {
            v *= alpha;
            if (EPI >= 1) v += bias[c];
            if (EPI == 2) v = 0.5f * v * (1.f + erff(v * 0.70710678118654752f));
            if (EPI == 3) v += R[(long long)r * ldc + c];
            if (RND) v = tf32r(v);
            C[(long long)r * ldc + c] = v;
        }
    };
    #pragma unroll
    for (int i = 0; i < 4; i++) {
        int r0 = m0 + wm + i * 16 + g;
        #pragma unroll
        for (int j = 0; j < 4; j++) {
            int c0 = n0 + wn + j * 8 + 2 * tg;
            emit(r0,     c0,     acc[i][j][0]);
            emit(r0,     c0 + 1, acc[i][j][1]);
            emit(r0 + 8, c0,     acc[i][j][2]);
            emit(r0 + 8, c0 + 1, acc[i][j][3]);
        }
    }
}

// ---------------- launch ----------------
extern "C" void kernel_launch(void* const* d_in, const int* in_sizes, int n_in,
                              void* d_out, int out_size) {
    const float* x    = (const float*)d_in[0];
    const float* ln1w = (const float*)d_in[1];
    const float* ln1b = (const float*)d_in[2];
    const float* Wq   = (const float*)d_in[3];
    const float* bq   = (const float*)d_in[4];
    const float* Wk   = (const float*)d_in[5];
    const float* bk   = (const float*)d_in[6];
    const float* Wv   = (const float*)d_in[7];
    const float* bv   = (const float*)d_in[8];
    const float* Wo   = (const float*)d_in[9];
    const float* bo   = (const float*)d_in[10];
    const float* ln2w = (const float*)d_in[11];
    const float* ln2b = (const float*)d_in[12];
    const float* W1   = (const float*)d_in[13];
    const float* b1   = (const float*)d_in[14];
    const float* W2   = (const float*)d_in[15];
    const float* b2   = (const float*)d_in[16];
    float* out = (float*)d_out;

    float *p_h, *p_qkv, *p_sc, *p_ctx, *p_x2, *p_ffn, *p_Wqkv, *p_bqkv, *p_Wo, *p_W1, *p_W2;
    cudaGetSymbolAddress((void**)&p_h,    g_h);
    cudaGetSymbolAddress((void**)&p_qkv,  g_qkv);
    cudaGetSymbolAddress((void**)&p_sc,   g_sc);
    cudaGetSymbolAddress((void**)&p_ctx,  g_ctx);
    cudaGetSymbolAddress((void**)&p_x2,   g_x2);
    cudaGetSymbolAddress((void**)&p_ffn,  g_ffn);
    cudaGetSymbolAddress((void**)&p_Wqkv, g_Wqkv);
    cudaGetSymbolAddress((void**)&p_bqkv, g_bqkv);
    cudaGetSymbolAddress((void**)&p_Wo,   g_Wo);
    cudaGetSymbolAddress((void**)&p_W1,   g_W1);
    cudaGetSymbolAddress((void**)&p_W2,   g_W2);

    // weight prep (tf32-rounded copies; avoids cvt in GEMM inner loop)
    pack_qkv_k<<<(CD * 3 * CD + 255) / 256, 256>>>(Wq, Wk, Wv, bq, bk, bv);
    round_copy_k<<<(CD * CD  + 255) / 256, 256>>>(p_Wo, Wo, CD * CD);
    round_copy_k<<<(CD * CFF + 255) / 256, 256>>>(p_W1, W1, CD * CFF);
    round_copy_k<<<(CFF * CD + 255) / 256, 256>>>(p_W2, W2, CFF * CD);

    // LN1
    ln_k<<<MALL, 256>>>(x, ln1w, ln1b, p_h);

    // QKV: [18464,768] x [768,2304] (+bias, rounded)
    {
        dim3 gr(3 * CD / BN, (MALL + BM - 1) / BM, 1);
        gemm_k<1, 0, 1><<<gr, 256>>>(p_h, p_Wqkv, p_qkv, p_bqkv, nullptr,
            MALL, 3 * CD, CD, CD, 3 * CD, 3 * CD, 1.f,
            1, 0, 0, 0, 0, 0, 0);
    }

    // scores = (q k^T)/8 per (b,h): batched, TRANSB
    {
        dim3 gr((CS + BN - 1) / BN, (CS + BM - 1) / BM, CB * CH);
        gemm_k<0, 1, 0><<<gr, 256>>>(p_qkv, p_qkv + CD, p_sc, nullptr, nullptr,
            CS, CS, CDH, 3 * CD, 3 * CD, SLD, 0.125f,
            CH, (long long)CS * 3 * CD, 64, (long long)CS * 3 * CD, 64,
            (long long)CH * CS * SLD, (long long)CS * SLD);
    }

    // softmax rows (in place, tf32-rounded)
    softmax_k<<<CB * CH * CS, 256>>>(p_sc);

    // ctx = probs @ V per (b,h)
    {
        dim3 gr(1, (CS + BM - 1) / BM, CB * CH);
        gemm_k<0, 0, 1><<<gr, 256>>>(p_sc, p_qkv + 2 * CD, p_ctx, nullptr, nullptr,
            CS, CDH, CS, SLD, 3 * CD, CD, 1.f,
            CH, (long long)CH * CS * SLD, (long long)CS * SLD,
            (long long)CS * 3 * CD, 64, (long long)CS * CD, 64);
    }

    // x2 = ctx @ Wo + bo + x
    {
        dim3 gr(CD / BN, (MALL + BM - 1) / BM, 1);
        gemm_k<3, 0, 0><<<gr, 256>>>(p_ctx, p_Wo, p_x2, bo, x,
            MALL, CD, CD, CD, CD, CD, 1.f,
            1, 0, 0, 0, 0, 0, 0);
    }

    // LN2 (reuse g_h)
    ln_k<<<MALL, 256>>>(p_x2, ln2w, ln2b, p_h);

    // ffn = GELU(h2 @ W1 + b1)
    {
        dim3 gr(CFF / BN, (MALL + BM - 1) / BM, 1);
        gemm_k<2, 0, 1><<<gr, 256>>>(p_h, p_W1, p_ffn, b1, nullptr,
            MALL, CFF, CD, CD, CFF, CFF, 1.f,
            1, 0, 0, 0, 0, 0, 0);
    }

    // out = ffn @ W2 + b2 + x2
    {
        dim3 gr(CD / BN, (MALL + BM - 1) / BM, 1);
        gemm_k<3, 0, 0><<<gr, 256>>>(p_ffn, p_W2, out, b2, p_x2,
            MALL, CD, CFF, CFF, CD, CD, 1.f,
            1, 0, 0, 0, 0, 0, 0);
    }
}

// round 3
// speedup vs baseline: 1.3984x; 1.3984x over previous
#include <cuda_runtime.h>
#include <cuda_fp16.h>
#include <cstdint>
#include <math.h>

#define DEVI __device__ __forceinline__

// ---------------- problem constants ----------------
constexpr int CB = 32, CS = 577, CD = 768, CH = 12, CDH = 64, CFF = 3072;
constexpr int MALL = CB * CS;            // 18464 rows
constexpr int SLDH = 608;                // padded scores ld (19*32)
constexpr float LNEPS = 1e-5f;

// ---------------- device scratch (allocation-free) ----------------
__device__ __half g_h   [MALL * CD];              // LN out (GEMM A)
__device__ __half g_qkv [MALL * 3 * CD];          // q|k|v fp16
__device__ __half g_sc  [(long long)CB * CH * CS * SLDH]; // scores/probs fp16
__device__ __half g_vt  [(long long)CB * CH * CDH * SLDH]; // V transposed [bh][e][t]
__device__ __half g_ctx [MALL * CD];              // attention ctx fp16
__device__ float  g_x2  [MALL * CD];              // x + attn_out (fp32 residual)
__device__ __half g_ffn [MALL * CFF];             // GELU out fp16
__device__ __half g_Wqkvt[3 * CD * CD];           // [2304][768] k-major
__device__ float  g_bqkv [3 * CD];
__device__ __half g_Wot  [CD * CD];               // [768][768] k-major
__device__ __half g_W1t  [CFF * CD];              // [3072][768]
__device__ __half g_W2t  [CD * CFF];              // [768][3072]

// ---------------- helpers ----------------
DEVI uint32_t smem_u32(const void* p) {
    uint32_t a;
    asm("{ .reg .u64 t; cvta.to.shared.u64 t, %1; cvt.u32.u64 %0, t; }" : "=r"(a) : "l"(p));
    return a;
}
DEVI void cpa16s(uint32_t dst, const void* g) {
    asm volatile("cp.async.cg.shared.global [%0], [%1], 16;" :: "r"(dst), "l"(g));
}
DEVI void cpa_commit() { asm volatile("cp.async.commit_group;"); }
DEVI void sts_zero16(uint32_t dst) {
    asm volatile("st.shared.v4.b32 [%0], {%1,%1,%1,%1};" :: "r"(dst), "r"(0));
}

DEVI float bsum(float v, float* sb) {
    #pragma unroll
    for (int o = 16; o > 0; o >>= 1) v += __shfl_xor_sync(0xffffffffu, v, o);
    __syncthreads();
    if ((threadIdx.x & 31) == 0) sb[threadIdx.x >> 5] = v;
    __syncthreads();
    float t = 0.f;
    #pragma unroll
    for (int i = 0; i < 8; i++) t += sb[i];
    return t;
}
DEVI float bmax(float v, float* sb) {
    #pragma unroll
    for (int o = 16; o > 0; o >>= 1) v = fmaxf(v, __shfl_xor_sync(0xffffffffu, v, o));
    __syncthreads();
    if ((threadIdx.x & 31) == 0) sb[threadIdx.x >> 5] = v;
    __syncthreads();
    float t = -1e30f;
    #pragma unroll
    for (int i = 0; i < 8; i++) t = fmaxf(t, sb[i]);
    return t;
}

// ---------------- weight prep ----------------
__global__ void transpose_h(const float* __restrict__ src, __half* __restrict__ dst,
                            int R, int C) {
    // dst[c][r] = half(src[r][c]); src ld=C, dst ld=R ; R,C multiples of 32
    __shared__ float t[32][33];
    int c0 = blockIdx.x * 32, r0 = blockIdx.y * 32;
    int tx = threadIdx.x, ty = threadIdx.y;
    #pragma unroll
    for (int i = 0; i < 32; i += 8)
        t[ty + i][tx] = src[(long long)(r0 + ty + i) * C + c0 + tx];
    __syncthreads();
    #pragma unroll
    for (int i = 0; i < 32; i += 8)
        dst[(long long)(c0 + ty + i) * R + r0 + tx] = __float2half_rn(t[tx][ty + i]);
}

__global__ void qkv_t_k(const float* __restrict__ Wq, const float* __restrict__ Wk,
                        const float* __restrict__ Wv) {
    // g_Wqkvt[n][k], n = which*768 + h*64 + e, src W[(h*768+k)*64 + e]
    __shared__ float t[32][33];
    int n0 = blockIdx.y * 32, k0 = blockIdx.x * 32;
    int which = n0 / CD;
    int c0 = n0 % CD, h = c0 >> 6, e0 = c0 & 63;
    const float* W = (which == 0) ? Wq : (which == 1) ? Wk : Wv;
    const float* base = W + (long long)h * CD * CDH;
    int tx = threadIdx.x, ty = threadIdx.y;
    #pragma unroll
    for (int i = 0; i < 32; i += 8)
        t[ty + i][tx] = base[(long long)(k0 + ty + i) * CDH + e0 + tx];
    __syncthreads();
    #pragma unroll
    for (int i = 0; i < 32; i += 8)
        g_Wqkvt[(long long)(n0 + ty + i) * CD + k0 + tx] = __float2half_rn(t[tx][ty + i]);
}

__global__ void bias_pack_k(const float* __restrict__ bq, const float* __restrict__ bk,
                            const float* __restrict__ bv) {
    int i = blockIdx.x * 256 + threadIdx.x;
    if (i < 3 * CD) {
        int w = i / CD, c = i % CD;
        g_bqkv[i] = ((w == 0) ? bq : (w == 1) ? bk : bv)[c];
    }
}

// V transpose: g_vt[bh][e][t] = g_qkv[(b*577+t)][1536 + h*64 + e], zero pad t>=577
__global__ void vt_k() {
    __shared__ __half t[32][33];
    int t0 = blockIdx.x * 32, e0 = blockIdx.y * 32;
    int bh = blockIdx.z;
    int b = bh / CH, h = bh % CH;
    int tx = threadIdx.x, ty = threadIdx.y;
    const __half* src = g_qkv + 2 * CD + (long long)h * CDH;
    #pragma unroll
    for (int i = 0; i < 32; i += 8) {
        int tt = t0 + ty + i;
        t[ty + i][tx] = (tt < CS)
            ? src[(long long)(b * CS + tt) * (3 * CD) + e0 + tx]
            : __float2half_rn(0.f);
    }
    __syncthreads();
    __half* dst = g_vt + (long long)bh * CDH * SLDH;
    #pragma unroll
    for (int i = 0; i < 32; i += 8)
        dst[(long long)(e0 + ty + i) * SLDH + t0 + tx] = t[tx][ty + i];
}

// ---------------- layer norm (fp32 in -> fp16 out) ----------------
__global__ void ln_k(const float* __restrict__ x, const float* __restrict__ w,
                     const float* __restrict__ b, __half* __restrict__ o) {
    __shared__ float sb[8];
    long long row = blockIdx.x;
    const float* xr = x + row * CD;
    float v[3];
    float s = 0.f;
    #pragma unroll
    for (int i = 0; i < 3; i++) { v[i] = xr[threadIdx.x + i * 256]; s += v[i]; }
    s = bsum(s, sb);
    float mu = s * (1.f / (float)CD);
    float q = 0.f;
    #pragma unroll
    for (int i = 0; i < 3; i++) { float d = v[i] - mu; q += d * d; }
    q = bsum(q, sb);
    float rs = rsqrtf(q * (1.f / (float)CD) + LNEPS);
    #pragma unroll
    for (int i = 0; i < 3; i++) {
        int c = threadIdx.x + i * 256;
        o[row * CD + c] = __float2half_rn((v[i] - mu) * rs * w[c] + b[c]);
    }
}

// ---------------- softmax (fp16 rows, ld=SLDH, writes pad zeros) ----------------
__global__ void softmax_k(__half* __restrict__ p) {
    __shared__ float sb[8];
    __half* row = p + (long long)blockIdx.x * SLDH;
    float v[3];
    #pragma unroll
    for (int i = 0; i < 3; i++) {
        int idx = threadIdx.x + i * 256;
        v[i] = (idx < CS) ? __half2float(row[idx]) : -1e30f;
    }
    float m = bmax(fmaxf(fmaxf(v[0], v[1]), v[2]), sb);
    float e[3];
    float s = 0.f;
    #pragma unroll
    for (int i = 0; i < 3; i++) {
        int idx = threadIdx.x + i * 256;
        e[i] = (idx < CS) ? expf(v[i] - m) : 0.f;
        s += e[i];
    }
    s = bsum(s, sb);
    float inv = 1.f / s;
    #pragma unroll
    for (int i = 0; i < 3; i++) {
        int idx = threadIdx.x + i * 256;
        if (idx < SLDH) row[idx] = __float2half_rn((idx < CS) ? e[i] * inv : 0.f);
    }
}

// =====================================================================
// fp16 mma.sync GEMM:  C[M,N] = alpha * A[M,K] * B[N,K]^T (+epilogue)
// A,B fp16 k-major. fp32 accumulate.
// EPI: 0 = alpha, half out                (scores / ctx)
//      1 = +bias, half out                (QKV)
//      2 = +bias, GELU, half out          (W1)
//      3 = +bias +residual, float out     (Wo, W2)
// Batch via blockIdx.z: zb=z/batchH, zh=z%batchH.
// =====================================================================
constexpr int BM = 128, BN = 128, BK = 32, NST = 3;
constexpr int LDS_H = BK + 8;             // 40 halves per row
constexpr int ATILE = BM * LDS_H;         // halves
constexpr int BTILE = BN * LDS_H;
constexpr int STG_H = ATILE + BTILE;      // 10240 halves = 20480 B
constexpr int DSMEM = NST * STG_H * 2;    // 61440 B

DEVI void mma16816(float* c, const uint32_t* a, const uint32_t* b) {
    asm volatile(
        "mma.sync.aligned.m16n8k16.row.col.f32.f16.f16.f32 "
        "{%0,%1,%2,%3},{%4,%5,%6,%7},{%8,%9},{%0,%1,%2,%3};"
        : "+f"(c[0]), "+f"(c[1]), "+f"(c[2]), "+f"(c[3])
        : "r"(a[0]), "r"(a[1]), "r"(a[2]), "r"(a[3]), "r"(b[0]), "r"(b[1]));
}

template <int EPI>
__global__ void __launch_bounds__(256, 2) hgemm(
    const __half* __restrict__ A, const __half* __restrict__ B, void* __restrict__ Cv,
    const float* __restrict__ bias, const float* __restrict__ res,
    int M, int N, int K, int lda, int ldb, int ldc, float alpha,
    int batchH, long long sAb, long long sAh, long long sBb, long long sBh,
    long long sCb, long long sCh)
{
    extern __shared__ __align__(16) __half sh[];
    uint32_t sbase = smem_u32(sh);

    int z = blockIdx.z;
    int zb = z / batchH, zh = z % batchH;
    A += zb * sAb + zh * sAh;
    B += zb * sBb + zh * sBh;
    long long coff = zb * sCb + zh * sCh;

    int m0 = blockIdx.y * BM, n0 = blockIdx.x * BN;
    int tid = threadIdx.x, lane = tid & 31, wid = tid >> 5;

    auto loadA = [&](int s, int k0) {
        uint32_t ab = sbase + (uint32_t)(s * STG_H) * 2;
        #pragma unroll
        for (int i = 0; i < 2; i++) {
            int v = tid + i * 256;
            int r = v >> 2, cq = (v & 3) << 3;          // halves
            uint32_t dst = ab + (uint32_t)(r * LDS_H + cq) * 2;
            int gm = m0 + r;
            if (gm < M) cpa16s(dst, A + (long long)gm * lda + k0 + cq);
            else        sts_zero16(dst);
        }
    };
    auto loadB = [&](int s, int k0) {
        uint32_t bb = sbase + (uint32_t)(s * STG_H + ATILE) * 2;
        #pragma unroll
        for (int i = 0; i < 2; i++) {
            int v = tid + i * 256;
            int r = v >> 2, cq = (v & 3) << 3;
            uint32_t dst = bb + (uint32_t)(r * LDS_H + cq) * 2;
            int gn = n0 + r;
            if (gn < N) cpa16s(dst, B + (long long)gn * ldb + k0 + cq);
            else        sts_zero16(dst);
        }
    };

    int wm = (wid >> 2) * 64;        // 0 / 64
    int wn = (wid & 3) * 32;         // 0,32,64,96
    int g = lane >> 2, tg = lane & 3;

    float acc[4][4][4];
    #pragma unroll
    for (int i = 0; i < 4; i++)
        #pragma unroll
        for (int j = 0; j < 4; j++)
            #pragma unroll
            for (int q = 0; q < 4; q++) acc[i][j][q] = 0.f;

    int nk = K / BK;
    #pragma unroll
    for (int s = 0; s < NST - 1; s++) { loadA(s, s * BK); loadB(s, s * BK); cpa_commit(); }

    for (int kt = 0; kt < nk; kt++) {
        if (kt + NST - 1 < nk) {
            int s = (kt + NST - 1) % NST;
            loadA(s, (kt + NST - 1) * BK);
            loadB(s, (kt + NST - 1) * BK);
        }
        cpa_commit();
        asm volatile("cp.async.wait_group %0;" :: "n"(NST - 1));
        __syncthreads();

        int st = kt % NST;
        const uint32_t* As32 = (const uint32_t*)(sh + st * STG_H);
        const uint32_t* Bs32 = (const uint32_t*)(sh + st * STG_H + ATILE);

        #pragma unroll
        for (int kc = 0; kc < 2; kc++) {               // two k16 steps
            int ko = kc * 8;                           // 32-bit units
            uint32_t af[4][4], bf[4][2];
            #pragma unroll
            for (int i = 0; i < 4; i++) {
                int r = wm + i * 16 + g;
                af[i][0] = As32[r * (LDS_H / 2) + ko + tg];
                af[i][1] = As32[(r + 8) * (LDS_H / 2) + ko + tg];
                af[i][2] = As32[r * (LDS_H / 2) + ko + tg + 4];
                af[i][3] = As32[(r + 8) * (LDS_H / 2) + ko + tg + 4];
            }
            #pragma unroll
            for (int j = 0; j < 4; j++) {
                int c = wn + j * 8 + g;
                bf[j][0] = Bs32[c * (LDS_H / 2) + ko + tg];
                bf[j][1] = Bs32[c * (LDS_H / 2) + ko + tg + 4];
            }
            #pragma unroll
            for (int i = 0; i < 4; i++)
                #pragma unroll
                for (int j = 0; j < 4; j++) mma16816(acc[i][j], af[i], bf[j]);
        }
        __syncthreads();
    }

    // epilogue
    __half* Ch = (__half*)Cv + coff;
    float*  Cf = (float*)Cv + coff;
    auto emit = [&](int r, int c, float v) {
        if (r < M && c < N) {
            v *= alpha;
            if (EPI >= 1) v += bias[c];
            if (EPI == 2) v = 0.5f * v * (1.f + erff(v * 0.70710678118654752f));
            if (EPI == 3) {
                v += res[(long long)r * ldc + c];
                Cf[(long long)r * ldc + c] = v;
            } else {
                Ch[(long long)r * ldc + c] = __float2half_rn(v);
            }
        }
    };
    #pragma unroll
    for (int i = 0; i < 4; i++) {
        int r0 = m0 + wm + i * 16 + g;
        #pragma unroll
        for (int j = 0; j < 4; j++) {
            int c0 = n0 + wn + j * 8 + 2 * tg;
            emit(r0,     c0,     acc[i][j][0]);
            emit(r0,     c0 + 1, acc[i][j][1]);
            emit(r0 + 8, c0,     acc[i][j][2]);
            emit(r0 + 8, c0 + 1, acc[i][j][3]);
        }
    }
}

// ---------------- launch ----------------
extern "C" void kernel_launch(void* const* d_in, const int* in_sizes, int n_in,
                              void* d_out, int out_size) {
    const float* x    = (const float*)d_in[0];
    const float* ln1w = (const float*)d_in[1];
    const float* ln1b = (const float*)d_in[2];
    const float* Wq   = (const float*)d_in[3];
    const float* bq   = (const float*)d_in[4];
    const float* Wk   = (const float*)d_in[5];
    const float* bk   = (const float*)d_in[6];
    const float* Wv   = (const float*)d_in[7];
    const float* bv   = (const float*)d_in[8];
    const float* Wo   = (const float*)d_in[9];
    const float* bo   = (const float*)d_in[10];
    const float* ln2w = (const float*)d_in[11];
    const float* ln2b = (const float*)d_in[12];
    const float* W1   = (const float*)d_in[13];
    const float* b1   = (const float*)d_in[14];
    const float* W2   = (const float*)d_in[15];
    const float* b2   = (const float*)d_in[16];
    float* out = (float*)d_out;

    __half *p_h, *p_qkv, *p_sc, *p_vt, *p_ctx, *p_ffn, *p_Wqkvt, *p_Wot, *p_W1t, *p_W2t;
    float *p_x2, *p_bqkv;
    cudaGetSymbolAddress((void**)&p_h,     g_h);
    cudaGetSymbolAddress((void**)&p_qkv,   g_qkv);
    cudaGetSymbolAddress((void**)&p_sc,    g_sc);
    cudaGetSymbolAddress((void**)&p_vt,    g_vt);
    cudaGetSymbolAddress((void**)&p_ctx,   g_ctx);
    cudaGetSymbolAddress((void**)&p_x2,    g_x2);
    cudaGetSymbolAddress((void**)&p_ffn,   g_ffn);
    cudaGetSymbolAddress((void**)&p_Wqkvt, g_Wqkvt);
    cudaGetSymbolAddress((void**)&p_bqkv,  g_bqkv);
    cudaGetSymbolAddress((void**)&p_Wot,   g_Wot);
    cudaGetSymbolAddress((void**)&p_W1t,   g_W1t);
    cudaGetSymbolAddress((void**)&p_W2t,   g_W2t);

    cudaFuncSetAttribute(hgemm<0>, cudaFuncAttributeMaxDynamicSharedMemorySize, DSMEM);
    cudaFuncSetAttribute(hgemm<1>, cudaFuncAttributeMaxDynamicSharedMemorySize, DSMEM);
    cudaFuncSetAttribute(hgemm<2>, cudaFuncAttributeMaxDynamicSharedMemorySize, DSMEM);
    cudaFuncSetAttribute(hgemm<3>, cudaFuncAttributeMaxDynamicSharedMemorySize, DSMEM);

    dim3 tb(32, 8);

    // weight prep (k-major fp16)
    qkv_t_k<<<dim3(CD / 32, 3 * CD / 32), tb>>>(Wq, Wk, Wv);
    bias_pack_k<<<(3 * CD + 255) / 256, 256>>>(bq, bk, bv);
    transpose_h<<<dim3(CD / 32, CD / 32), tb>>>(Wo, p_Wot, CD, CD);
    transpose_h<<<dim3(CFF / 32, CD / 32), tb>>>(W1, p_W1t, CD, CFF);
    transpose_h<<<dim3(CD / 32, CFF / 32), tb>>>(W2, p_W2t, CFF, CD);

    int mtiles = (MALL + BM - 1) / BM;   // 145

    // LN1
    ln_k<<<MALL, 256>>>(x, ln1w, ln1b, p_h);

    // QKV: [18464,768] x [2304,768]^T -> fp16 qkv (+bias)
    hgemm<1><<<dim3(3 * CD / BN, mtiles), 256, DSMEM>>>(
        p_h, p_Wqkvt, p_qkv, p_bqkv, nullptr,
        MALL, 3 * CD, CD, CD, CD, 3 * CD, 1.f,
        1, 0, 0, 0, 0, 0, 0);

    // V transpose for ctx GEMM
    vt_k<<<dim3(SLDH / 32, CDH / 32, CB * CH), tb>>>();

    // scores = (q k^T)/8 per (b,h) -> fp16, ld=SLDH
    {
        dim3 gr((CS + BN - 1) / BN, (CS + BM - 1) / BM, CB * CH);
        hgemm<0><<<gr, 256, DSMEM>>>(
            p_qkv, p_qkv + CD, p_sc, nullptr, nullptr,
            CS, CS, CDH, 3 * CD, 3 * CD, SLDH, 0.125f,
            CH, (long long)CS * 3 * CD, CDH, (long long)CS * 3 * CD, CDH,
            (long long)CH * CS * SLDH, (long long)CS * SLDH);
    }

    softmax_k<<<CB * CH * CS, 256>>>(p_sc);

    // ctx = probs @ Vt^T per (b,h): M=577, N=64, K=SLDH (zero-padded)
    {
        dim3 gr(1, (CS + BM - 1) / BM, CB * CH);
        hgemm<0><<<gr, 256, DSMEM>>>(
            p_sc, p_vt, p_ctx, nullptr, nullptr,
            CS, CDH, SLDH, SLDH, SLDH, CD, 1.f,
            CH, (long long)CH * CS * SLDH, (long long)CS * SLDH,
            (long long)CH * CDH * SLDH, (long long)CDH * SLDH,
            (long long)CS * CD, CDH);
    }

    // x2 = ctx @ Wo + bo + x  (fp32 out)
    hgemm<3><<<dim3(CD / BN, mtiles), 256, DSMEM>>>(
        p_ctx, p_Wot, p_x2, bo, x,
        MALL, CD, CD, CD, CD, CD, 1.f,
        1, 0, 0, 0, 0, 0, 0);

    // LN2
    ln_k<<<MALL, 256>>>(p_x2, ln2w, ln2b, p_h);

    // ffn = GELU(h2 @ W1 + b1) -> fp16
    hgemm<2><<<dim3(CFF / BN, mtiles), 256, DSMEM>>>(
        p_h, p_W1t, p_ffn, b1, nullptr,
        MALL, CFF, CD, CD, CD, CFF, 1.f,
        1, 0, 0, 0, 0, 0, 0);

    // out = ffn @ W2 + b2 + x2  (fp32 out)
    hgemm<3><<<dim3(CD / BN, mtiles), 256, DSMEM>>>(
        p_ffn, p_W2t, out, b2, p_x2,
        MALL, CD, CFF, CFF, CFF, CD, 1.f,
        1, 0, 0, 0, 0, 0, 0);
}

// round 4
// speedup vs baseline: 1.8863x; 1.3489x over previous
#include <cuda_runtime.h>
#include <cuda_fp16.h>
#include <cstdint>
#include <math.h>

#define DEVI __device__ __forceinline__

// ---------------- problem constants ----------------
constexpr int CB = 32, CS = 577, CD = 768, CH = 12, CDH = 64, CFF = 3072;
constexpr int MALL = CB * CS;            // 18464 rows
constexpr float LNEPS = 1e-5f;

// ---------------- device scratch (allocation-free) ----------------
__device__ __half g_h   [MALL * CD];              // LN out (GEMM A)
__device__ __half g_qkv [MALL * 3 * CD];          // q|k|v fp16, row ld = 2304
__device__ __half g_ctx [MALL * CD];              // attention ctx fp16
__device__ float  g_x2  [MALL * CD];              // x + attn_out (fp32 residual)
__device__ __half g_ffn [MALL * CFF];             // GELU out fp16
__device__ __half g_Wqkvt[3 * CD * CD];           // [2304][768] k-major
__device__ float  g_bqkv [3 * CD];
__device__ __half g_Wot  [CD * CD];               // [768][768] k-major
__device__ __half g_W1t  [CFF * CD];              // [3072][768]
__device__ __half g_W2t  [CD * CFF];              // [768][3072]

// ---------------- helpers ----------------
DEVI uint32_t smem_u32(const void* p) {
    uint32_t a;
    asm("{ .reg .u64 t; cvta.to.shared.u64 t, %1; cvt.u32.u64 %0, t; }" : "=r"(a) : "l"(p));
    return a;
}
DEVI void cpa16s(uint32_t dst, const void* g) {
    asm volatile("cp.async.cg.shared.global [%0], [%1], 16;" :: "r"(dst), "l"(g));
}
DEVI void cpa_commit() { asm volatile("cp.async.commit_group;"); }
DEVI void sts_zero16(uint32_t dst) {
    asm volatile("st.shared.v4.b32 [%0], {%1,%1,%1,%1};" :: "r"(dst), "r"(0));
}
DEVI void ldm_x4(uint32_t* r, uint32_t addr) {
    asm volatile("ldmatrix.sync.aligned.m8n8.x4.shared.b16 {%0,%1,%2,%3}, [%4];"
        : "=r"(r[0]), "=r"(r[1]), "=r"(r[2]), "=r"(r[3]) : "r"(addr));
}
DEVI void ldm_x4_t(uint32_t* r, uint32_t addr) {
    asm volatile("ldmatrix.sync.aligned.m8n8.x4.trans.shared.b16 {%0,%1,%2,%3}, [%4];"
        : "=r"(r[0]), "=r"(r[1]), "=r"(r[2]), "=r"(r[3]) : "r"(addr));
}
DEVI void mma16816(float* c, const uint32_t* a, const uint32_t* b) {
    asm volatile(
        "mma.sync.aligned.m16n8k16.row.col.f32.f16.f16.f32 "
        "{%0,%1,%2,%3},{%4,%5,%6,%7},{%8,%9},{%0,%1,%2,%3};"
        : "+f"(c[0]), "+f"(c[1]), "+f"(c[2]), "+f"(c[3])
        : "r"(a[0]), "r"(a[1]), "r"(a[2]), "r"(a[3]), "r"(b[0]), "r"(b[1]));
}

DEVI float bsum(float v, float* sb) {
    #pragma unroll
    for (int o = 16; o > 0; o >>= 1) v += __shfl_xor_sync(0xffffffffu, v, o);
    __syncthreads();
    if ((threadIdx.x & 31) == 0) sb[threadIdx.x >> 5] = v;
    __syncthreads();
    float t = 0.f;
    #pragma unroll
    for (int i = 0; i < 8; i++) t += sb[i];
    return t;
}

// ---------------- weight prep ----------------
__global__ void transpose_h(const float* __restrict__ src, __half* __restrict__ dst,
                            int R, int C) {
    __shared__ float t[32][33];
    int c0 = blockIdx.x * 32, r0 = blockIdx.y * 32;
    int tx = threadIdx.x, ty = threadIdx.y;
    #pragma unroll
    for (int i = 0; i < 32; i += 8)
        t[ty + i][tx] = src[(long long)(r0 + ty + i) * C + c0 + tx];
    __syncthreads();
    #pragma unroll
    for (int i = 0; i < 32; i += 8)
        dst[(long long)(c0 + ty + i) * R + r0 + tx] = __float2half_rn(t[tx][ty + i]);
}

__global__ void qkv_t_k(const float* __restrict__ Wq, const float* __restrict__ Wk,
                        const float* __restrict__ Wv) {
    __shared__ float t[32][33];
    int n0 = blockIdx.y * 32, k0 = blockIdx.x * 32;
    int which = n0 / CD;
    int c0 = n0 % CD, h = c0 >> 6, e0 = c0 & 63;
    const float* W = (which == 0) ? Wq : (which == 1) ? Wk : Wv;
    const float* base = W + (long long)h * CD * CDH;
    int tx = threadIdx.x, ty = threadIdx.y;
    #pragma unroll
    for (int i = 0; i < 32; i += 8)
        t[ty + i][tx] = base[(long long)(k0 + ty + i) * CDH + e0 + tx];
    __syncthreads();
    #pragma unroll
    for (int i = 0; i < 32; i += 8)
        g_Wqkvt[(long long)(n0 + ty + i) * CD + k0 + tx] = __float2half_rn(t[tx][ty + i]);
}

__global__ void bias_pack_k(const float* __restrict__ bq, const float* __restrict__ bk,
                            const float* __restrict__ bv) {
    int i = blockIdx.x * 256 + threadIdx.x;
    if (i < 3 * CD) {
        int w = i / CD, c = i % CD;
        g_bqkv[i] = ((w == 0) ? bq : (w == 1) ? bk : bv)[c];
    }
}

// ---------------- layer norm (fp32 in -> fp16 out) ----------------
__global__ void ln_k(const float* __restrict__ x, const float* __restrict__ w,
                     const float* __restrict__ b, __half* __restrict__ o) {
    __shared__ float sb[8];
    long long row = blockIdx.x;
    const float* xr = x + row * CD;
    float v[3];
    float s = 0.f;
    #pragma unroll
    for (int i = 0; i < 3; i++) { v[i] = xr[threadIdx.x + i * 256]; s += v[i]; }
    s = bsum(s, sb);
    float mu = s * (1.f / (float)CD);
    float q = 0.f;
    #pragma unroll
    for (int i = 0; i < 3; i++) { float d = v[i] - mu; q += d * d; }
    q = bsum(q, sb);
    float rs = rsqrtf(q * (1.f / (float)CD) + LNEPS);
    #pragma unroll
    for (int i = 0; i < 3; i++) {
        int c = threadIdx.x + i * 256;
        o[row * CD + c] = __float2half_rn((v[i] - mu) * rs * w[c] + b[c]);
    }
}

// =====================================================================
// big-tile fp16 GEMM: C[M,N] = A[M,K] * B[N,K]^T (+epilogue)
// 128x256x32, 8 warps x (64x64), ldmatrix fragments, 3-stage cp.async.
// EPI: 1 = +bias, half out; 2 = +bias GELU, half out; 3 = +bias+res, float out
// =====================================================================
constexpr int BM = 128, BN = 256, BK = 32, NST = 3;
constexpr int LDS_H = BK + 8;              // 40 halves per row (80 B)
constexpr int ATILE = BM * LDS_H;          // halves
constexpr int BTILE = BN * LDS_H;
constexpr int STG_H = ATILE + BTILE;       // 15360 halves
constexpr int DSMEM = NST * STG_H * 2;     // 92160 B

template <int EPI>
__global__ void __launch_bounds__(256, 1) hgemm2(
    const __half* __restrict__ A, const __half* __restrict__ B, void* __restrict__ Cv,
    const float* __restrict__ bias, const float* __restrict__ res,
    int M, int N, int K)
{
    extern __shared__ __align__(16) __half sh[];
    uint32_t sbase = smem_u32(sh);

    int m0 = blockIdx.y * BM;
    long long n0 = (long long)blockIdx.x * BN;
    int tid = threadIdx.x, lane = tid & 31, wid = tid >> 5;

    auto loadA = [&](int s, int k0) {
        uint32_t ab = sbase + (uint32_t)(s * STG_H) * 2;
        #pragma unroll
        for (int i = 0; i < 2; i++) {
            int v = tid + i * 256;
            int r = v >> 2, cq = (v & 3) << 3;
            uint32_t dst = ab + (uint32_t)(r * LDS_H + cq) * 2;
            int gm = m0 + r;
            if (gm < M) cpa16s(dst, A + (long long)gm * K + k0 + cq);
            else        sts_zero16(dst);
        }
    };
    auto loadB = [&](int s, int k0) {
        uint32_t bb = sbase + (uint32_t)(s * STG_H + ATILE) * 2;
        #pragma unroll
        for (int i = 0; i < 4; i++) {
            int v = tid + i * 256;
            int r = v >> 2, cq = (v & 3) << 3;
            uint32_t dst = bb + (uint32_t)(r * LDS_H + cq) * 2;
            cpa16s(dst, B + (n0 + r) * K + k0 + cq);
        }
    };

    int wm = (wid & 1) * 64;
    int wn = (wid >> 1) * 64;
    int g = lane >> 2, tg = lane & 3;

    // ldmatrix per-lane row/col offsets
    int arow = ((lane >> 3) & 1) * 8 + (lane & 7);
    int acol = (lane >> 4) * 8;
    int brow = ((lane >> 4) & 1) * 8 + (lane & 7);
    int bcol = ((lane >> 3) & 1) * 8;

    float acc[4][8][4];
    #pragma unroll
    for (int i = 0; i < 4; i++)
        #pragma unroll
        for (int j = 0; j < 8; j++)
            #pragma unroll
            for (int q = 0; q < 4; q++) acc[i][j][q] = 0.f;

    int nk = K / BK;
    #pragma unroll
    for (int s = 0; s < NST - 1; s++) { loadA(s, s * BK); loadB(s, s * BK); cpa_commit(); }

    for (int kt = 0; kt < nk; kt++) {
        if (kt + NST - 1 < nk) {
            int s = (kt + NST - 1) % NST;
            loadA(s, (kt + NST - 1) * BK);
            loadB(s, (kt + NST - 1) * BK);
        }
        cpa_commit();
        asm volatile("cp.async.wait_group %0;" :: "n"(NST - 1));
        __syncthreads();

        int st = kt % NST;
        uint32_t abase = sbase + (uint32_t)(st * STG_H) * 2;
        uint32_t bbase = sbase + (uint32_t)(st * STG_H + ATILE) * 2;

        #pragma unroll
        for (int kc = 0; kc < 2; kc++) {
            uint32_t af[4][4];
            #pragma unroll
            for (int i = 0; i < 4; i++)
                ldm_x4(af[i], abase + (uint32_t)((wm + i * 16 + arow) * LDS_H + kc * 16 + acol) * 2);
            #pragma unroll
            for (int p = 0; p < 4; p++) {
                uint32_t bf[4];
                ldm_x4(bf, bbase + (uint32_t)((wn + p * 16 + brow) * LDS_H + kc * 16 + bcol) * 2);
                #pragma unroll
                for (int i = 0; i < 4; i++) {
                    mma16816(acc[i][2 * p],     af[i], bf);
                    mma16816(acc[i][2 * p + 1], af[i], bf + 2);
                }
            }
        }
        __syncthreads();
    }

    // epilogue
    __half* Ch = (__half*)Cv;
    float*  Cf = (float*)Cv;
    auto emit = [&](int r, long long c, float v) {
        if (r < M) {
            if (EPI >= 1) v += bias[c];
            if (EPI == 2) v = 0.5f * v * (1.f + erff(v * 0.70710678118654752f));
            if (EPI == 3) {
                v += res[(long long)r * N + c];
                Cf[(long long)r * N + c] = v;
            } else {
                Ch[(long long)r * N + c] = __float2half_rn(v);
            }
        }
    };
    #pragma unroll
    for (int i = 0; i < 4; i++) {
        int r0 = m0 + wm + i * 16 + g;
        #pragma unroll
        for (int j = 0; j < 8; j++) {
            long long c0 = n0 + wn + j * 8 + 2 * tg;
            emit(r0,     c0,     acc[i][j][0]);
            emit(r0,     c0 + 1, acc[i][j][1]);
            emit(r0 + 8, c0,     acc[i][j][2]);
            emit(r0 + 8, c0 + 1, acc[i][j][3]);
        }
    }
}

// =====================================================================
// flash attention: per (qtile, b*h). 256 threads, 8 warps x 16 q-rows.
// Q tile 128x64 (frags in regs, pre-scaled by 1/8), K/V tiles 128x64
// double-buffered. Online softmax in registers. Out: ctx fp16.
// =====================================================================
constexpr int FP = 72;                    // padded halves per row
constexpr int FTILE = 128 * FP;           // halves per tile buffer
constexpr int FSMEM = 5 * FTILE * 2;      // Q + 2K + 2V = 92160 B
constexpr int NQT = (CS + 127) / 128;     // 5

__global__ void __launch_bounds__(256, 1) flash_k(
    const __half* __restrict__ qkv, __half* __restrict__ ctx)
{
    extern __shared__ __align__(16) __half fs[];
    uint32_t sbase = smem_u32(fs);

    int q0 = blockIdx.x * 128;
    int bh = blockIdx.y;
    int b = bh / CH, h = bh % CH;
    int tid = threadIdx.x, lane = tid & 31, wid = tid >> 5;
    int g = lane >> 2, tg = lane & 3;

    const __half* qbase = qkv + (long long)b * CS * (3 * CD) + h * CDH;

    uint32_t sQ = sbase;
    uint32_t sK[2] = { sbase + FTILE * 2u, sbase + FTILE * 4u };
    uint32_t sV[2] = { sbase + FTILE * 6u, sbase + FTILE * 8u };

    // ---- load tile helper: 128 rows x 64 halves (8 chunks of 16B/row) ----
    auto load_tile = [&](uint32_t dstb, const __half* src, int t0) {
        #pragma unroll
        for (int i = 0; i < 4; i++) {
            int v = tid + i * 256;
            int r = v >> 3, c8 = (v & 7) << 3;
            uint32_t dst = dstb + (uint32_t)(r * FP + c8) * 2;
            if (t0 + r < CS) cpa16s(dst, src + (long long)(t0 + r) * (3 * CD) + c8);
            else             sts_zero16(dst);
        }
    };

    // Q
    load_tile(sQ, qbase, q0);
    // prefetch KV tile 0
    load_tile(sK[0], qbase + CD, 0);
    load_tile(sV[0], qbase + 2 * CD, 0);
    cpa_commit();

    // ldmatrix lane offsets
    int arow = ((lane >> 3) & 1) * 8 + (lane & 7);
    int acol = (lane >> 4) * 8;
    int brow = ((lane >> 4) & 1) * 8 + (lane & 7);
    int bcol = ((lane >> 3) & 1) * 8;
    int trow = ((lane >> 3) & 1) * 8 + (lane & 7);   // trans: t row
    int tcol = (lane >> 4) * 8;                      // trans: e col

    asm volatile("cp.async.wait_group 0;");
    __syncthreads();

    // Q fragments (scaled by 1/8)
    uint32_t af_q[4][4];
    {
        __half2 sc = __float2half2_rn(0.125f);
        #pragma unroll
        for (int ks = 0; ks < 4; ks++) {
            ldm_x4(af_q[ks], sQ + (uint32_t)((wid * 16 + arow) * FP + ks * 16 + acol) * 2);
            #pragma unroll
            for (int q = 0; q < 4; q++) {
                __half2 v = *(__half2*)&af_q[ks][q];
                v = __hmul2(v, sc);
                af_q[ks][q] = *(uint32_t*)&v;
            }
        }
    }

    float acc_o[8][4];
    #pragma unroll
    for (int j = 0; j < 8; j++)
        #pragma unroll
        for (int q = 0; q < 4; q++) acc_o[j][q] = 0.f;
    float m_lo = -1e30f, m_hi = -1e30f, l_lo = 0.f, l_hi = 0.f;

    for (int t = 0; t < NQT; t++) {
        int buf = t & 1;
        __syncthreads();                       // all warps done with buf (from t-2)
        if (t + 1 < NQT) {
            load_tile(sK[buf ^ 1], qbase + CD, (t + 1) * 128);
            load_tile(sV[buf ^ 1], qbase + 2 * CD, (t + 1) * 128);
            cpa_commit();
            asm volatile("cp.async.wait_group 1;");
        } else {
            asm volatile("cp.async.wait_group 0;");
        }
        __syncthreads();

        int valid = CS - t * 128;              // >=128 except last (65)

        // ---- S = Qw (16x64) . K^T (128x64) ----
        float s[16][4];
        #pragma unroll
        for (int j = 0; j < 16; j++)
            #pragma unroll
            for (int q = 0; q < 4; q++) s[j][q] = 0.f;
        #pragma unroll
        for (int ks = 0; ks < 4; ks++) {
            #pragma unroll
            for (int p = 0; p < 8; p++) {
                uint32_t bf[4];
                ldm_x4(bf, sK[buf] + (uint32_t)((p * 16 + brow) * FP + ks * 16 + bcol) * 2);
                mma16816(s[2 * p],     af_q[ks], bf);
                mma16816(s[2 * p + 1], af_q[ks], bf + 2);
            }
        }

        // mask invalid cols (last tile)
        if (valid < 128) {
            #pragma unroll
            for (int j = 0; j < 16; j++) {
                int c = j * 8 + 2 * tg;
                if (c     >= valid) { s[j][0] = -1e30f; s[j][2] = -1e30f; }
                if (c + 1 >= valid) { s[j][1] = -1e30f; s[j][3] = -1e30f; }
            }
        }

        // row stats
        float mx_lo = -1e30f, mx_hi = -1e30f;
        #pragma unroll
        for (int j = 0; j < 16; j++) {
            mx_lo = fmaxf(mx_lo, fmaxf(s[j][0], s[j][1]));
            mx_hi = fmaxf(mx_hi, fmaxf(s[j][2], s[j][3]));
        }
        mx_lo = fmaxf(mx_lo, __shfl_xor_sync(0xffffffffu, mx_lo, 1));
        mx_lo = fmaxf(mx_lo, __shfl_xor_sync(0xffffffffu, mx_lo, 2));
        mx_hi = fmaxf(mx_hi, __shfl_xor_sync(0xffffffffu, mx_hi, 1));
        mx_hi = fmaxf(mx_hi, __shfl_xor_sync(0xffffffffu, mx_hi, 2));

        float mn_lo = fmaxf(m_lo, mx_lo), mn_hi = fmaxf(m_hi, mx_hi);
        float corr_lo = __expf(m_lo - mn_lo), corr_hi = __expf(m_hi - mn_hi);
        m_lo = mn_lo; m_hi = mn_hi;

        float sum_lo = 0.f, sum_hi = 0.f;
        uint32_t pf[8][4];                     // P fragments: kt 0..7
        #pragma unroll
        for (int kt = 0; kt < 8; kt++) {
            float p00 = __expf(s[2 * kt][0] - mn_lo);
            float p01 = __expf(s[2 * kt][1] - mn_lo);
            float p02 = __expf(s[2 * kt][2] - mn_hi);
            float p03 = __expf(s[2 * kt][3] - mn_hi);
            float p10 = __expf(s[2 * kt + 1][0] - mn_lo);
            float p11 = __expf(s[2 * kt + 1][1] - mn_lo);
            float p12 = __expf(s[2 * kt + 1][2] - mn_hi);
            float p13 = __expf(s[2 * kt + 1][3] - mn_hi);
            sum_lo += p00 + p01 + p10 + p11;
            sum_hi += p02 + p03 + p12 + p13;
            __half2 h0 = __floats2half2_rn(p00, p01);
            __half2 h1 = __floats2half2_rn(p02, p03);
            __half2 h2 = __floats2half2_rn(p10, p11);
            __half2 h3 = __floats2half2_rn(p12, p13);
            pf[kt][0] = *(uint32_t*)&h0;
            pf[kt][1] = *(uint32_t*)&h1;
            pf[kt][2] = *(uint32_t*)&h2;
            pf[kt][3] = *(uint32_t*)&h3;
        }
        sum_lo += __shfl_xor_sync(0xffffffffu, sum_lo, 1);
        sum_lo += __shfl_xor_sync(0xffffffffu, sum_lo, 2);
        sum_hi += __shfl_xor_sync(0xffffffffu, sum_hi, 1);
        sum_hi += __shfl_xor_sync(0xffffffffu, sum_hi, 2);
        l_lo = l_lo * corr_lo + sum_lo;
        l_hi = l_hi * corr_hi + sum_hi;

        // rescale O
        #pragma unroll
        for (int j = 0; j < 8; j++) {
            acc_o[j][0] *= corr_lo; acc_o[j][1] *= corr_lo;
            acc_o[j][2] *= corr_hi; acc_o[j][3] *= corr_hi;
        }

        // ---- O += P (16x128) . V (128x64) ----
        #pragma unroll
        for (int kt = 0; kt < 8; kt++) {
            #pragma unroll
            for (int ep = 0; ep < 2; ep++) {
                uint32_t bf[4];
                ldm_x4_t(bf, sV[buf] + (uint32_t)((kt * 16 + trow) * FP + ep * 32 + tcol) * 2);
                mma16816(acc_o[4 * ep],     pf[kt], bf);
                mma16816(acc_o[4 * ep + 1], pf[kt], bf + 2);
            }
            #pragma unroll
            for (int ep = 0; ep < 2; ep++) {
                uint32_t bf[4];
                ldm_x4_t(bf, sV[buf] + (uint32_t)((kt * 16 + trow) * FP + ep * 32 + 16 + tcol) * 2);
                mma16816(acc_o[4 * ep + 2], pf[kt], bf);
                mma16816(acc_o[4 * ep + 3], pf[kt], bf + 2);
            }
        }
    }

    // ---- write ctx ----
    float il_lo = 1.f / l_lo, il_hi = 1.f / l_hi;
    int r_lo = q0 + wid * 16 + g;
    int r_hi = r_lo + 8;
    #pragma unroll
    for (int j = 0; j < 8; j++) {
        int c = j * 8 + 2 * tg;
        if (r_lo < CS) {
            __half2 v = __floats2half2_rn(acc_o[j][0] * il_lo, acc_o[j][1] * il_lo);
            *(__half2*)(ctx + (long long)(b * CS + r_lo) * CD + h * CDH + c) = v;
        }
        if (r_hi < CS) {
            __half2 v = __floats2half2_rn(acc_o[j][2] * il_hi, acc_o[j][3] * il_hi);
            *(__half2*)(ctx + (long long)(b * CS + r_hi) * CD + h * CDH + c) = v;
        }
    }
}

// NOTE on V-frag index mapping: acc_o[j2] covers e cols j2*8..j2*8+7.
// ldm_x4_t at e-offset (ep*32 + {0,16}) yields matrices for e tiles
// {4ep, 4ep+1} and {4ep+2, 4ep+3} respectively, matching acc_o[4ep..4ep+3].

// ---------------- launch ----------------
extern "C" void kernel_launch(void* const* d_in, const int* in_sizes, int n_in,
                              void* d_out, int out_size) {
    const float* x    = (const float*)d_in[0];
    const float* ln1w = (const float*)d_in[1];
    const float* ln1b = (const float*)d_in[2];
    const float* Wq   = (const float*)d_in[3];
    const float* bq   = (const float*)d_in[4];
    const float* Wk   = (const float*)d_in[5];
    const float* bk   = (const float*)d_in[6];
    const float* Wv   = (const float*)d_in[7];
    const float* bv   = (const float*)d_in[8];
    const float* Wo   = (const float*)d_in[9];
    const float* bo   = (const float*)d_in[10];
    const float* ln2w = (const float*)d_in[11];
    const float* ln2b = (const float*)d_in[12];
    const float* W1   = (const float*)d_in[13];
    const float* b1   = (const float*)d_in[14];
    const float* W2   = (const float*)d_in[15];
    const float* b2   = (const float*)d_in[16];
    float* out = (float*)d_out;

    __half *p_h, *p_qkv, *p_ctx, *p_ffn, *p_Wqkvt, *p_Wot, *p_W1t, *p_W2t;
    float *p_x2, *p_bqkv;
    cudaGetSymbolAddress((void**)&p_h,     g_h);
    cudaGetSymbolAddress((void**)&p_qkv,   g_qkv);
    cudaGetSymbolAddress((void**)&p_ctx,   g_ctx);
    cudaGetSymbolAddress((void**)&p_x2,    g_x2);
    cudaGetSymbolAddress((void**)&p_ffn,   g_ffn);
    cudaGetSymbolAddress((void**)&p_Wqkvt, g_Wqkvt);
    cudaGetSymbolAddress((void**)&p_bqkv,  g_bqkv);
    cudaGetSymbolAddress((void**)&p_Wot,   g_Wot);
    cudaGetSymbolAddress((void**)&p_W1t,   g_W1t);
    cudaGetSymbolAddress((void**)&p_W2t,   g_W2t);

    cudaFuncSetAttribute(hgemm2<1>, cudaFuncAttributeMaxDynamicSharedMemorySize, DSMEM);
    cudaFuncSetAttribute(hgemm2<2>, cudaFuncAttributeMaxDynamicSharedMemorySize, DSMEM);
    cudaFuncSetAttribute(hgemm2<3>, cudaFuncAttributeMaxDynamicSharedMemorySize, DSMEM);
    cudaFuncSetAttribute(flash_k,   cudaFuncAttributeMaxDynamicSharedMemorySize, FSMEM);

    dim3 tb(32, 8);

    // weight prep (k-major fp16)
    qkv_t_k<<<dim3(CD / 32, 3 * CD / 32), tb>>>(Wq, Wk, Wv);
    bias_pack_k<<<(3 * CD + 255) / 256, 256>>>(bq, bk, bv);
    transpose_h<<<dim3(CD / 32, CD / 32), tb>>>(Wo, p_Wot, CD, CD);
    transpose_h<<<dim3(CFF / 32, CD / 32), tb>>>(W1, p_W1t, CD, CFF);
    transpose_h<<<dim3(CD / 32, CFF / 32), tb>>>(W2, p_W2t, CFF, CD);

    int mtiles = (MALL + BM - 1) / BM;   // 145

    // LN1
    ln_k<<<MALL, 256>>>(x, ln1w, ln1b, p_h);

    // QKV: [18464,768] x [2304,768]^T (+bias) -> fp16
    hgemm2<1><<<dim3(3 * CD / BN, mtiles), 256, DSMEM>>>(
        p_h, p_Wqkvt, p_qkv, p_bqkv, nullptr, MALL, 3 * CD, CD);

    // fused attention -> ctx fp16
    flash_k<<<dim3(NQT, CB * CH), 256, FSMEM>>>(p_qkv, p_ctx);

    // x2 = ctx @ Wo + bo + x  (fp32 out)
    hgemm2<3><<<dim3(CD / BN, mtiles), 256, DSMEM>>>(
        p_ctx, p_Wot, p_x2, bo, x, MALL, CD, CD);

    // LN2
    ln_k<<<MALL, 256>>>(p_x2, ln2w, ln2b, p_h);

    // ffn = GELU(h2 @ W1 + b1) -> fp16
    hgemm2<2><<<dim3(CFF / BN, mtiles), 256, DSMEM>>>(
        p_h, p_W1t, p_ffn, b1, nullptr, MALL, CFF, CD);

    // out = ffn @ W2 + b2 + x2  (fp32 out)
    hgemm2<3><<<dim3(CD / BN, mtiles), 256, DSMEM>>>(
        p_ffn, p_W2t, out, b2, p_x2, MALL, CD, CFF);
}

// round 7
// speedup vs baseline: 2.1656x; 1.1481x over previous
#include <cuda_runtime.h>
#include <cuda_fp16.h>
#include <cstdint>
#include <math.h>

#define DEVI __device__ __forceinline__

// ---------------- problem constants ----------------
constexpr int CB = 32, CS = 577, CD = 768, CH = 12, CDH = 64, CFF = 3072;
constexpr int MALL = CB * CS;            // 18464 rows
constexpr float LNEPS = 1e-5f;

// ---------------- device scratch (allocation-free) ----------------
__device__ __half g_h   [MALL * CD];              // LN out (GEMM A)
__device__ __half g_qkv [MALL * 3 * CD];          // q|k|v fp16, row ld = 2304
__device__ __half g_ctx [MALL * CD];              // attention ctx fp16
__device__ float  g_x2  [MALL * CD];              // x + attn_out (fp32 residual)
__device__ __half g_ffn [MALL * CFF];             // GELU out fp16
__device__ __half g_Wqkvt[3 * CD * CD];           // [2304][768] k-major
__device__ float  g_bqkv [3 * CD];
__device__ __half g_Wot  [CD * CD];               // [768][768] k-major
__device__ __half g_W1t  [CFF * CD];              // [3072][768]
__device__ __half g_W2t  [CD * CFF];              // [768][3072]

// ---------------- helpers ----------------
DEVI uint32_t smem_u32(const void* p) {
    uint32_t a;
    asm("{ .reg .u64 t; cvta.to.shared.u64 t, %1; cvt.u32.u64 %0, t; }" : "=r"(a) : "l"(p));
    return a;
}
DEVI void cpa16s(uint32_t dst, const void* g) {
    asm volatile("cp.async.cg.shared.global [%0], [%1], 16;" :: "r"(dst), "l"(g));
}
DEVI void cpa_commit() { asm volatile("cp.async.commit_group;"); }
DEVI void sts_zero16(uint32_t dst) {
    asm volatile("st.shared.v4.b32 [%0], {%1,%1,%1,%1};" :: "r"(dst), "r"(0));
}
DEVI void ldm_x4(uint32_t* r, uint32_t addr) {
    asm volatile("ldmatrix.sync.aligned.m8n8.x4.shared.b16 {%0,%1,%2,%3}, [%4];"
        : "=r"(r[0]), "=r"(r[1]), "=r"(r[2]), "=r"(r[3]) : "r"(addr));
}
DEVI void ldm_x4_t(uint32_t* r, uint32_t addr) {
    asm volatile("ldmatrix.sync.aligned.m8n8.x4.trans.shared.b16 {%0,%1,%2,%3}, [%4];"
        : "=r"(r[0]), "=r"(r[1]), "=r"(r[2]), "=r"(r[3]) : "r"(addr));
}
DEVI void mma16816(float* c, const uint32_t* a, const uint32_t* b) {
    asm volatile(
        "mma.sync.aligned.m16n8k16.row.col.f32.f16.f16.f32 "
        "{%0,%1,%2,%3},{%4,%5,%6,%7},{%8,%9},{%0,%1,%2,%3};"
        : "+f"(c[0]), "+f"(c[1]), "+f"(c[2]), "+f"(c[3])
        : "r"(a[0]), "r"(a[1]), "r"(a[2]), "r"(a[3]), "r"(b[0]), "r"(b[1]));
}

DEVI float bsum(float v, float* sb) {
    #pragma unroll
    for (int o = 16; o > 0; o >>= 1) v += __shfl_xor_sync(0xffffffffu, v, o);
    __syncthreads();
    if ((threadIdx.x & 31) == 0) sb[threadIdx.x >> 5] = v;
    __syncthreads();
    float t = 0.f;
    #pragma unroll
    for (int i = 0; i < 8; i++) t += sb[i];
    return t;
}

// ---------------- weight prep ----------------
__global__ void transpose_h(const float* __restrict__ src, __half* __restrict__ dst,
                            int R, int C) {
    __shared__ float t[32][33];
    int c0 = blockIdx.x * 32, r0 = blockIdx.y * 32;
    int tx = threadIdx.x, ty = threadIdx.y;
    #pragma unroll
    for (int i = 0; i < 32; i += 8)
        t[ty + i][tx] = src[(long long)(r0 + ty + i) * C + c0 + tx];
    __syncthreads();
    #pragma unroll
    for (int i = 0; i < 32; i += 8)
        dst[(long long)(c0 + ty + i) * R + r0 + tx] = __float2half_rn(t[tx][ty + i]);
}

__global__ void qkv_t_k(const float* __restrict__ Wq, const float* __restrict__ Wk,
                        const float* __restrict__ Wv) {
    __shared__ float t[32][33];
    int n0 = blockIdx.y * 32, k0 = blockIdx.x * 32;
    int which = n0 / CD;
    int c0 = n0 % CD, h = c0 >> 6, e0 = c0 & 63;
    const float* W = (which == 0) ? Wq : (which == 1) ? Wk : Wv;
    const float* base = W + (long long)h * CD * CDH;
    int tx = threadIdx.x, ty = threadIdx.y;
    #pragma unroll
    for (int i = 0; i < 32; i += 8)
        t[ty + i][tx] = base[(long long)(k0 + ty + i) * CDH + e0 + tx];
    __syncthreads();
    #pragma unroll
    for (int i = 0; i < 32; i += 8)
        g_Wqkvt[(long long)(n0 + ty + i) * CD + k0 + tx] = __float2half_rn(t[tx][ty + i]);
}

__global__ void bias_pack_k(const float* __restrict__ bq, const float* __restrict__ bk,
                            const float* __restrict__ bv) {
    int i = blockIdx.x * 256 + threadIdx.x;
    if (i < 3 * CD) {
        int w = i / CD, c = i % CD;
        g_bqkv[i] = ((w == 0) ? bq : (w == 1) ? bk : bv)[c];
    }
}

// ---------------- layer norm (fp32 in -> fp16 out) ----------------
__global__ void ln_k(const float* __restrict__ x, const float* __restrict__ w,
                     const float* __restrict__ b, __half* __restrict__ o) {
    __shared__ float sb[8];
    long long row = blockIdx.x;
    const float* xr = x + row * CD;
    float v[3];
    float s = 0.f;
    #pragma unroll
    for (int i = 0; i < 3; i++) { v[i] = xr[threadIdx.x + i * 256]; s += v[i]; }
    s = bsum(s, sb);
    float mu = s * (1.f / (float)CD);
    float q = 0.f;
    #pragma unroll
    for (int i = 0; i < 3; i++) { float d = v[i] - mu; q += d * d; }
    q = bsum(q, sb);
    float rs = rsqrtf(q * (1.f / (float)CD) + LNEPS);
    #pragma unroll
    for (int i = 0; i < 3; i++) {
        int c = threadIdx.x + i * 256;
        o[row * CD + c] = __float2half_rn((v[i] - mu) * rs * w[c] + b[c]);
    }
}

// =====================================================================
// big-tile fp16 GEMM: C[M,N] = A[M,K] * B[N,K]^T (+epilogue)
// 128x256x64, 8 warps x (64x64), ldmatrix fragments, 3-stage cp.async,
// ONE __syncthreads per k-tile (CUTLASS multistage ordering).
// EPI: 1 = +bias, half out; 2 = +bias GELU, half out; 3 = +bias+res, float out
// =====================================================================
constexpr int BM = 128, BN = 256, BK = 64, NST = 3;
constexpr int LDS_H = BK + 8;              // 72 halves per row (144 B)
constexpr int ATILE = BM * LDS_H;          // halves
constexpr int BTILE = BN * LDS_H;
constexpr int STG_H = ATILE + BTILE;       // 27648 halves = 55296 B
constexpr int DSMEM = NST * STG_H * 2;     // 165888 B

template <int EPI>
__global__ void __launch_bounds__(256, 1) hgemm2(
    const __half* __restrict__ A, const __half* __restrict__ B, void* __restrict__ Cv,
    const float* __restrict__ bias, const float* __restrict__ res,
    int M, int N, int K)
{
    extern __shared__ __align__(16) __half sh[];
    uint32_t sbase = smem_u32(sh);

    int m0 = blockIdx.y * BM;
    long long n0 = (long long)blockIdx.x * BN;
    int tid = threadIdx.x, lane = tid & 31, wid = tid >> 5;

    auto loadA = [&](int s, int k0) {
        uint32_t ab = sbase + (uint32_t)(s * STG_H) * 2;
        #pragma unroll
        for (int i = 0; i < 4; i++) {
            int v = tid + i * 256;
            int r = v >> 3, cq = (v & 7) << 3;
            uint32_t dst = ab + (uint32_t)(r * LDS_H + cq) * 2;
            int gm = m0 + r;
            if (gm < M) cpa16s(dst, A + (long long)gm * K + k0 + cq);
            else        sts_zero16(dst);
        }
    };
    auto loadB = [&](int s, int k0) {
        uint32_t bb = sbase + (uint32_t)(s * STG_H + ATILE) * 2;
        #pragma unroll
        for (int i = 0; i < 8; i++) {
            int v = tid + i * 256;
            int r = v >> 3, cq = (v & 7) << 3;
            uint32_t dst = bb + (uint32_t)(r * LDS_H + cq) * 2;
            cpa16s(dst, B + (n0 + r) * K + k0 + cq);
        }
    };

    int wm = (wid & 1) * 64;
    int wn = (wid >> 1) * 64;
    int g = lane >> 2, tg = lane & 3;

    // ldmatrix per-lane row/col offsets
    int arow = ((lane >> 3) & 1) * 8 + (lane & 7);
    int acol = (lane >> 4) * 8;
    int brow = ((lane >> 4) & 1) * 8 + (lane & 7);
    int bcol = ((lane >> 3) & 1) * 8;

    float acc[4][8][4];
    #pragma unroll
    for (int i = 0; i < 4; i++)
        #pragma unroll
        for (int j = 0; j < 8; j++)
            #pragma unroll
            for (int q = 0; q < 4; q++) acc[i][j][q] = 0.f;

    int nk = K / BK;
    #pragma unroll
    for (int s = 0; s < NST - 1; s++) { loadA(s, s * BK); loadB(s, s * BK); cpa_commit(); }

    for (int kt = 0; kt < nk; kt++) {
        asm volatile("cp.async.wait_group %0;" :: "n"(NST - 2));
        __syncthreads();
        // issue loads for stage kt+NST-1 (overwrites the stage read at kt-1;
        // all warps passed that compute before this sync)
        if (kt + NST - 1 < nk) {
            int s = (kt + NST - 1) % NST;
            loadA(s, (kt + NST - 1) * BK);
            loadB(s, (kt + NST - 1) * BK);
        }
        cpa_commit();

        int st = kt % NST;
        uint32_t abase = sbase + (uint32_t)(st * STG_H) * 2;
        uint32_t bbase = sbase + (uint32_t)(st * STG_H + ATILE) * 2;

        #pragma unroll
        for (int kc = 0; kc < 4; kc++) {
            uint32_t af[4][4];
            #pragma unroll
            for (int i = 0; i < 4; i++)
                ldm_x4(af[i], abase + (uint32_t)((wm + i * 16 + arow) * LDS_H + kc * 16 + acol) * 2);
            #pragma unroll
            for (int p = 0; p < 4; p++) {
                uint32_t bf[4];
                ldm_x4(bf, bbase + (uint32_t)((wn + p * 16 + brow) * LDS_H + kc * 16 + bcol) * 2);
                #pragma unroll
                for (int i = 0; i < 4; i++) {
                    mma16816(acc[i][2 * p],     af[i], bf);
                    mma16816(acc[i][2 * p + 1], af[i], bf + 2);
                }
            }
        }
    }

    // epilogue
    __half* Ch = (__half*)Cv;
    float*  Cf = (float*)Cv;
    auto emit = [&](int r, long long c, float v) {
        if (r < M) {
            if (EPI >= 1) v += bias[c];
            if (EPI == 2) v = 0.5f * v * (1.f + erff(v * 0.70710678118654752f));
            if (EPI == 3) {
                v += res[(long long)r * N + c];
                Cf[(long long)r * N + c] = v;
            } else {
                Ch[(long long)r * N + c] = __float2half_rn(v);
            }
        }
    };
    #pragma unroll
    for (int i = 0; i < 4; i++) {
        int r0 = m0 + wm + i * 16 + g;
        #pragma unroll
        for (int j = 0; j < 8; j++) {
            long long c0 = n0 + wn + j * 8 + 2 * tg;
            emit(r0,     c0,     acc[i][j][0]);
            emit(r0,     c0 + 1, acc[i][j][1]);
            emit(r0 + 8, c0,     acc[i][j][2]);
            emit(r0 + 8, c0 + 1, acc[i][j][3]);
        }
    }
}

// =====================================================================
// flash attention: per (qtile, b*h). 256 threads, 8 warps x 16 q-rows.
// =====================================================================
constexpr int FP = 72;                    // padded halves per row
constexpr int FTILE = 128 * FP;           // halves per tile buffer
constexpr int FSMEM = 5 * FTILE * 2;      // Q + 2K + 2V = 92160 B
constexpr int NQT = (CS + 127) / 128;     // 5

__global__ void __launch_bounds__(256, 1) flash_k(
    const __half* __restrict__ qkv, __half* __restrict__ ctx)
{
    extern __shared__ __align__(16) __half fs[];
    uint32_t sbase = smem_u32(fs);

    int q0 = blockIdx.x * 128;
    int bh = blockIdx.y;
    int b = bh / CH, h = bh % CH;
    int tid = threadIdx.x, lane = tid & 31, wid = tid >> 5;
    int g = lane >> 2, tg = lane & 3;

    const __half* qbase = qkv + (long long)b * CS * (3 * CD) + h * CDH;

    uint32_t sQ = sbase;
    uint32_t sK[2] = { sbase + FTILE * 2u, sbase + FTILE * 4u };
    uint32_t sV[2] = { sbase + FTILE * 6u, sbase + FTILE * 8u };

    auto load_tile = [&](uint32_t dstb, const __half* src, int t0) {
        #pragma unroll
        for (int i = 0; i < 4; i++) {
            int v = tid + i * 256;
            int r = v >> 3, c8 = (v & 7) << 3;
            uint32_t dst = dstb + (uint32_t)(r * FP + c8) * 2;
            if (t0 + r < CS) cpa16s(dst, src + (long long)(t0 + r) * (3 * CD) + c8);
            else             sts_zero16(dst);
        }
    };

    load_tile(sQ, qbase, q0);
    load_tile(sK[0], qbase + CD, 0);
    load_tile(sV[0], qbase + 2 * CD, 0);
    cpa_commit();

    int arow = ((lane >> 3) & 1) * 8 + (lane & 7);
    int acol = (lane >> 4) * 8;
    int brow = ((lane >> 4) & 1) * 8 + (lane & 7);
    int bcol = ((lane >> 3) & 1) * 8;
    int trow = ((lane >> 3) & 1) * 8 + (lane & 7);
    int tcol = (lane >> 4) * 8;

    asm volatile("cp.async.wait_group 0;");
    __syncthreads();

    uint32_t af_q[4][4];
    {
        __half2 sc = __float2half2_rn(0.125f);
        #pragma unroll
        for (int ks = 0; ks < 4; ks++) {
            ldm_x4(af_q[ks], sQ + (uint32_t)((wid * 16 + arow) * FP + ks * 16 + acol) * 2);
            #pragma unroll
            for (int q = 0; q < 4; q++) {
                __half2 v = *(__half2*)&af_q[ks][q];
                v = __hmul2(v, sc);
                af_q[ks][q] = *(uint32_t*)&v;
            }
        }
    }

    float acc_o[8][4];
    #pragma unroll
    for (int j = 0; j < 8; j++)
        #pragma unroll
        for (int q = 0; q < 4; q++) acc_o[j][q] = 0.f;
    float m_lo = -1e30f, m_hi = -1e30f, l_lo = 0.f, l_hi = 0.f;

    for (int t = 0; t < NQT; t++) {
        int buf = t & 1;
        __syncthreads();
        if (t + 1 < NQT) {
            load_tile(sK[buf ^ 1], qbase + CD, (t + 1) * 128);
            load_tile(sV[buf ^ 1], qbase + 2 * CD, (t + 1) * 128);
            cpa_commit();
            asm volatile("cp.async.wait_group 1;");
        } else {
            asm volatile("cp.async.wait_group 0;");
        }
        __syncthreads();

        int valid = CS - t * 128;

        float s[16][4];
        #pragma unroll
        for (int j = 0; j < 16; j++)
            #pragma unroll
            for (int q = 0; q < 4; q++) s[j][q] = 0.f;
        #pragma unroll
        for (int ks = 0; ks < 4; ks++) {
            #pragma unroll
            for (int p = 0; p < 8; p++) {
                uint32_t bf[4];
                ldm_x4(bf, sK[buf] + (uint32_t)((p * 16 + brow) * FP + ks * 16 + bcol) * 2);
                mma16816(s[2 * p],     af_q[ks], bf);
                mma16816(s[2 * p + 1], af_q[ks], bf + 2);
            }
        }

        if (valid < 128) {
            #pragma unroll
            for (int j = 0; j < 16; j++) {
                int c = j * 8 + 2 * tg;
                if (c     >= valid) { s[j][0] = -1e30f; s[j][2] = -1e30f; }
                if (c + 1 >= valid) { s[j][1] = -1e30f; s[j][3] = -1e30f; }
            }
        }

        float mx_lo = -1e30f, mx_hi = -1e30f;
        #pragma unroll
        for (int j = 0; j < 16; j++) {
            mx_lo = fmaxf(mx_lo, fmaxf(s[j][0], s[j][1]));
            mx_hi = fmaxf(mx_hi, fmaxf(s[j][2], s[j][3]));
        }
        mx_lo = fmaxf(mx_lo, __shfl_xor_sync(0xffffffffu, mx_lo, 1));
        mx_lo = fmaxf(mx_lo, __shfl_xor_sync(0xffffffffu, mx_lo, 2));
        mx_hi = fmaxf(mx_hi, __shfl_xor_sync(0xffffffffu, mx_hi, 1));
        mx_hi = fmaxf(mx_hi, __shfl_xor_sync(0xffffffffu, mx_hi, 2));

        float mn_lo = fmaxf(m_lo, mx_lo), mn_hi = fmaxf(m_hi, mx_hi);
        float corr_lo = __expf(m_lo - mn_lo), corr_hi = __expf(m_hi - mn_hi);
        m_lo = mn_lo; m_hi = mn_hi;

        float sum_lo = 0.f, sum_hi = 0.f;
        uint32_t pf[8][4];
        #pragma unroll
        for (int kt = 0; kt < 8; kt++) {
            float p00 = __expf(s[2 * kt][0] - mn_lo);
            float p01 = __expf(s[2 * kt][1] - mn_lo);
            float p02 = __expf(s[2 * kt][2] - mn_hi);
            float p03 = __expf(s[2 * kt][3] - mn_hi);
            float p10 = __expf(s[2 * kt + 1][0] - mn_lo);
            float p11 = __expf(s[2 * kt + 1][1] - mn_lo);
            float p12 = __expf(s[2 * kt + 1][2] - mn_hi);
            float p13 = __expf(s[2 * kt + 1][3] - mn_hi);
            sum_lo += p00 + p01 + p10 + p11;
            sum_hi += p02 + p03 + p12 + p13;
            __half2 h0 = __floats2half2_rn(p00, p01);
            __half2 h1 = __floats2half2_rn(p02, p03);
            __half2 h2 = __floats2half2_rn(p10, p11);
            __half2 h3 = __floats2half2_rn(p12, p13);
            pf[kt][0] = *(uint32_t*)&h0;
            pf[kt][1] = *(uint32_t*)&h1;
            pf[kt][2] = *(uint32_t*)&h2;
            pf[kt][3] = *(uint32_t*)&h3;
        }
        sum_lo += __shfl_xor_sync(0xffffffffu, sum_lo, 1);
        sum_lo += __shfl_xor_sync(0xffffffffu, sum_lo, 2);
        sum_hi += __shfl_xor_sync(0xffffffffu, sum_hi, 1);
        sum_hi += __shfl_xor_sync(0xffffffffu, sum_hi, 2);
        l_lo = l_lo * corr_lo + sum_lo;
        l_hi = l_hi * corr_hi + sum_hi;

        #pragma unroll
        for (int j = 0; j < 8; j++) {
            acc_o[j][0] *= corr_lo; acc_o[j][1] *= corr_lo;
            acc_o[j][2] *= corr_hi; acc_o[j][3] *= corr_hi;
        }

        #pragma unroll
        for (int kt = 0; kt < 8; kt++) {
            #pragma unroll
            for (int ep = 0; ep < 2; ep++) {
                uint32_t bf[4];
                ldm_x4_t(bf, sV[buf] + (uint32_t)((kt * 16 + trow) * FP + ep * 32 + tcol) * 2);
                mma16816(acc_o[4 * ep],     pf[kt], bf);
                mma16816(acc_o[4 * ep + 1], pf[kt], bf + 2);
            }
            #pragma unroll
            for (int ep = 0; ep < 2; ep++) {
                uint32_t bf[4];
                ldm_x4_t(bf, sV[buf] + (uint32_t)((kt * 16 + trow) * FP + ep * 32 + 16 + tcol) * 2);
                mma16816(acc_o[4 * ep + 2], pf[kt], bf);
                mma16816(acc_o[4 * ep + 3], pf[kt], bf + 2);
            }
        }
    }

    float il_lo = 1.f / l_lo, il_hi = 1.f / l_hi;
    int r_lo = q0 + wid * 16 + g;
    int r_hi = r_lo + 8;
    #pragma unroll
    for (int j = 0; j < 8; j++) {
        int c = j * 8 + 2 * tg;
        if (r_lo < CS) {
            __half2 v = __floats2half2_rn(acc_o[j][0] * il_lo, acc_o[j][1] * il_lo);
            *(__half2*)(ctx + (long long)(b * CS + r_lo) * CD + h * CDH + c) = v;
        }
        if (r_hi < CS) {
            __half2 v = __floats2half2_rn(acc_o[j][2] * il_hi, acc_o[j][3] * il_hi);
            *(__half2*)(ctx + (long long)(b * CS + r_hi) * CD + h * CDH + c) = v;
        }
    }
}

// ---------------- launch ----------------
extern "C" void kernel_launch(void* const* d_in, const int* in_sizes, int n_in,
                              void* d_out, int out_size) {
    const float* x    = (const float*)d_in[0];
    const float* ln1w = (const float*)d_in[1];
    const float* ln1b = (const float*)d_in[2];
    const float* Wq   = (const float*)d_in[3];
    const float* bq   = (const float*)d_in[4];
    const float* Wk   = (const float*)d_in[5];
    const float* bk   = (const float*)d_in[6];
    const float* Wv   = (const float*)d_in[7];
    const float* bv   = (const float*)d_in[8];
    const float* Wo   = (const float*)d_in[9];
    const float* bo   = (const float*)d_in[10];
    const float* ln2w = (const float*)d_in[11];
    const float* ln2b = (const float*)d_in[12];
    const float* W1   = (const float*)d_in[13];
    const float* b1   = (const float*)d_in[14];
    const float* W2   = (const float*)d_in[15];
    const float* b2   = (const float*)d_in[16];
    float* out = (float*)d_out;

    __half *p_h, *p_qkv, *p_ctx, *p_ffn, *p_Wqkvt, *p_Wot, *p_W1t, *p_W2t;
    float *p_x2, *p_bqkv;
    cudaGetSymbolAddress((void**)&p_h,     g_h);
    cudaGetSymbolAddress((void**)&p_qkv,   g_qkv);
    cudaGetSymbolAddress((void**)&p_ctx,   g_ctx);
    cudaGetSymbolAddress((void**)&p_x2,    g_x2);
    cudaGetSymbolAddress((void**)&p_ffn,   g_ffn);
    cudaGetSymbolAddress((void**)&p_Wqkvt, g_Wqkvt);
    cudaGetSymbolAddress((void**)&p_bqkv,  g_bqkv);
    cudaGetSymbolAddress((void**)&p_Wot,   g_Wot);
    cudaGetSymbolAddress((void**)&p_W1t,   g_W1t);
    cudaGetSymbolAddress((void**)&p_W2t,   g_W2t);

    cudaFuncSetAttribute(hgemm2<1>, cudaFuncAttributeMaxDynamicSharedMemorySize, DSMEM);
    cudaFuncSetAttribute(hgemm2<2>, cudaFuncAttributeMaxDynamicSharedMemorySize, DSMEM);
    cudaFuncSetAttribute(hgemm2<3>, cudaFuncAttributeMaxDynamicSharedMemorySize, DSMEM);
    cudaFuncSetAttribute(flash_k,   cudaFuncAttributeMaxDynamicSharedMemorySize, FSMEM);

    dim3 tb(32, 8);

    // weight prep (k-major fp16)
    qkv_t_k<<<dim3(CD / 32, 3 * CD / 32), tb>>>(Wq, Wk, Wv);
    bias_pack_k<<<(3 * CD + 255) / 256, 256>>>(bq, bk, bv);
    transpose_h<<<dim3(CD / 32, CD / 32), tb>>>(Wo, p_Wot, CD, CD);
    transpose_h<<<dim3(CFF / 32, CD / 32), tb>>>(W1, p_W1t, CD, CFF);
    transpose_h<<<dim3(CD / 32, CFF / 32), tb>>>(W2, p_W2t, CFF, CD);

    int mtiles = (MALL + BM - 1) / BM;   // 145

    // LN1
    ln_k<<<MALL, 256>>>(x, ln1w, ln1b, p_h);

    // QKV: [18464,768] x [2304,768]^T (+bias) -> fp16
    hgemm2<1><<<dim3(3 * CD / BN, mtiles), 256, DSMEM>>>(
        p_h, p_Wqkvt, p_qkv, p_bqkv, nullptr, MALL, 3 * CD, CD);

    // fused attention -> ctx fp16
    flash_k<<<dim3(NQT, CB * CH), 256, FSMEM>>>(p_qkv, p_ctx);

    // x2 = ctx @ Wo + bo + x  (fp32 out)
    hgemm2<3><<<dim3(CD / BN, mtiles), 256, DSMEM>>>(
        p_ctx, p_Wot, p_x2, bo, x, MALL, CD, CD);

    // LN2
    ln_k<<<MALL, 256>>>(p_x2, ln2w, ln2b, p_h);

    // ffn = GELU(h2 @ W1 + b1) -> fp16
    hgemm2<2><<<dim3(CFF / BN, mtiles), 256, DSMEM>>>(
        p_h, p_W1t, p_ffn, b1, nullptr, MALL, CFF, CD);

    // out = ffn @ W2 + b2 + x2  (fp32 out)
    hgemm2<3><<<dim3(CD / BN, mtiles), 256, DSMEM>>>(
        p_ffn, p_W2t, out, b2, p_x2, MALL, CD, CFF);
}

// round 8
// speedup vs baseline: 2.1946x; 1.0134x over previous
#include <cuda_runtime.h>
#include <cuda_fp16.h>
#include <cstdint>
#include <math.h>

#define DEVI __device__ __forceinline__

// ---------------- problem constants ----------------
constexpr int CB = 32, CS = 577, CD = 768, CH = 12, CDH = 64, CFF = 3072;
constexpr int MALL = CB * CS;            // 18464 rows
constexpr float LNEPS = 1e-5f;

// ---------------- device scratch (allocation-free) ----------------
__device__ __half g_h   [MALL * CD];              // LN out (GEMM A)
__device__ __half g_qkv [MALL * 3 * CD];          // q|k|v fp16, row ld = 2304
__device__ __half g_ctx [MALL * CD];              // attention ctx fp16
__device__ float  g_x2  [MALL * CD];              // x + attn_out (fp32 residual)
__device__ __half g_ffn [MALL * CFF];             // GELU out fp16
__device__ __half g_Wqkvt[3 * CD * CD];           // [2304][768] k-major
__device__ float  g_bqkv [3 * CD];
__device__ __half g_Wot  [CD * CD];               // [768][768] k-major
__device__ __half g_W1t  [CFF * CD];              // [3072][768]
__device__ __half g_W2t  [CD * CFF];              // [768][3072]

// ---------------- helpers ----------------
DEVI uint32_t smem_u32(const void* p) {
    uint32_t a;
    asm("{ .reg .u64 t; cvta.to.shared.u64 t, %1; cvt.u32.u64 %0, t; }" : "=r"(a) : "l"(p));
    return a;
}
DEVI void cpa16s(uint32_t dst, const void* g) {
    asm volatile("cp.async.cg.shared.global [%0], [%1], 16;" :: "r"(dst), "l"(g));
}
DEVI void cpa_commit() { asm volatile("cp.async.commit_group;"); }
DEVI void sts_zero16(uint32_t dst) {
    asm volatile("st.shared.v4.b32 [%0], {%1,%1,%1,%1};" :: "r"(dst), "r"(0));
}
DEVI void ldm_x4(uint32_t* r, uint32_t addr) {
    asm volatile("ldmatrix.sync.aligned.m8n8.x4.shared.b16 {%0,%1,%2,%3}, [%4];"
        : "=r"(r[0]), "=r"(r[1]), "=r"(r[2]), "=r"(r[3]) : "r"(addr));
}
DEVI void ldm_x4_t(uint32_t* r, uint32_t addr) {
    asm volatile("ldmatrix.sync.aligned.m8n8.x4.trans.shared.b16 {%0,%1,%2,%3}, [%4];"
        : "=r"(r[0]), "=r"(r[1]), "=r"(r[2]), "=r"(r[3]) : "r"(addr));
}
DEVI void mma16816(float* c, const uint32_t* a, const uint32_t* b) {
    asm volatile(
        "mma.sync.aligned.m16n8k16.row.col.f32.f16.f16.f32 "
        "{%0,%1,%2,%3},{%4,%5,%6,%7},{%8,%9},{%0,%1,%2,%3};"
        : "+f"(c[0]), "+f"(c[1]), "+f"(c[2]), "+f"(c[3])
        : "r"(a[0]), "r"(a[1]), "r"(a[2]), "r"(a[3]), "r"(b[0]), "r"(b[1]));
}

DEVI float bsum(float v, float* sb) {
    #pragma unroll
    for (int o = 16; o > 0; o >>= 1) v += __shfl_xor_sync(0xffffffffu, v, o);
    __syncthreads();
    if ((threadIdx.x & 31) == 0) sb[threadIdx.x >> 5] = v;
    __syncthreads();
    float t = 0.f;
    #pragma unroll
    for (int i = 0; i < 8; i++) t += sb[i];
    return t;
}

// ---------------- weight prep ----------------
__global__ void transpose_h(const float* __restrict__ src, __half* __restrict__ dst,
                            int R, int C) {
    __shared__ float t[32][33];
    int c0 = blockIdx.x * 32, r0 = blockIdx.y * 32;
    int tx = threadIdx.x, ty = threadIdx.y;
    #pragma unroll
    for (int i = 0; i < 32; i += 8)
        t[ty + i][tx] = src[(long long)(r0 + ty + i) * C + c0 + tx];
    __syncthreads();
    #pragma unroll
    for (int i = 0; i < 32; i += 8)
        dst[(long long)(c0 + ty + i) * R + r0 + tx] = __float2half_rn(t[tx][ty + i]);
}

__global__ void qkv_t_k(const float* __restrict__ Wq, const float* __restrict__ Wk,
                        const float* __restrict__ Wv) {
    __shared__ float t[32][33];
    int n0 = blockIdx.y * 32, k0 = blockIdx.x * 32;
    int which = n0 / CD;
    int c0 = n0 % CD, h = c0 >> 6, e0 = c0 & 63;
    const float* W = (which == 0) ? Wq : (which == 1) ? Wk : Wv;
    const float* base = W + (long long)h * CD * CDH;
    int tx = threadIdx.x, ty = threadIdx.y;
    #pragma unroll
    for (int i = 0; i < 32; i += 8)
        t[ty + i][tx] = base[(long long)(k0 + ty + i) * CDH + e0 + tx];
    __syncthreads();
    #pragma unroll
    for (int i = 0; i < 32; i += 8)
        g_Wqkvt[(long long)(n0 + ty + i) * CD + k0 + tx] = __float2half_rn(t[tx][ty + i]);
}

__global__ void bias_pack_k(const float* __restrict__ bq, const float* __restrict__ bk,
                            const float* __restrict__ bv) {
    int i = blockIdx.x * 256 + threadIdx.x;
    if (i < 3 * CD) {
        int w = i / CD, c = i % CD;
        g_bqkv[i] = ((w == 0) ? bq : (w == 1) ? bk : bv)[c];
    }
}

// ---------------- layer norm (fp32 in -> fp16 out) ----------------
__global__ void ln_k(const float* __restrict__ x, const float* __restrict__ w,
                     const float* __restrict__ b, __half* __restrict__ o) {
    __shared__ float sb[8];
    long long row = blockIdx.x;
    const float* xr = x + row * CD;
    float v[3];
    float s = 0.f;
    #pragma unroll
    for (int i = 0; i < 3; i++) { v[i] = xr[threadIdx.x + i * 256]; s += v[i]; }
    s = bsum(s, sb);
    float mu = s * (1.f / (float)CD);
    float q = 0.f;
    #pragma unroll
    for (int i = 0; i < 3; i++) { float d = v[i] - mu; q += d * d; }
    q = bsum(q, sb);
    float rs = rsqrtf(q * (1.f / (float)CD) + LNEPS);
    #pragma unroll
    for (int i = 0; i < 3; i++) {
        int c = threadIdx.x + i * 256;
        o[row * CD + c] = __float2half_rn((v[i] - mu) * rs * w[c] + b[c]);
    }
}

// =====================================================================
// big-tile fp16 GEMM: C[M,N] = A[M,K] * B[N,K]^T (+epilogue)
// 128x256x64, 16 warps x (32x64), ldmatrix fragments, 3-stage cp.async,
// ONE __syncthreads per k-tile (CUTLASS multistage ordering).
// EPI: 1 = +bias, half out; 2 = +bias GELU, half out; 3 = +bias+res, float out
// =====================================================================
constexpr int BM = 128, BN = 256, BK = 64, NST = 3;
constexpr int NTHR = 512;
constexpr int LDS_H = BK + 8;              // 72 halves per row (144 B)
constexpr int ATILE = BM * LDS_H;          // halves
constexpr int BTILE = BN * LDS_H;
constexpr int STG_H = ATILE + BTILE;       // 27648 halves = 55296 B
constexpr int DSMEM = NST * STG_H * 2;     // 165888 B

template <int EPI>
__global__ void __launch_bounds__(NTHR, 1) hgemm2(
    const __half* __restrict__ A, const __half* __restrict__ B, void* __restrict__ Cv,
    const float* __restrict__ bias, const float* __restrict__ res,
    int M, int N, int K)
{
    extern __shared__ __align__(16) __half sh[];
    uint32_t sbase = smem_u32(sh);

    int m0 = blockIdx.y * BM;
    long long n0 = (long long)blockIdx.x * BN;
    int tid = threadIdx.x, lane = tid & 31, wid = tid >> 5;

    auto loadA = [&](int s, int k0) {
        uint32_t ab = sbase + (uint32_t)(s * STG_H) * 2;
        #pragma unroll
        for (int i = 0; i < 2; i++) {
            int v = tid + i * NTHR;
            int r = v >> 3, cq = (v & 7) << 3;
            uint32_t dst = ab + (uint32_t)(r * LDS_H + cq) * 2;
            int gm = m0 + r;
            if (gm < M) cpa16s(dst, A + (long long)gm * K + k0 + cq);
            else        sts_zero16(dst);
        }
    };
    auto loadB = [&](int s, int k0) {
        uint32_t bb = sbase + (uint32_t)(s * STG_H + ATILE) * 2;
        #pragma unroll
        for (int i = 0; i < 4; i++) {
            int v = tid + i * NTHR;
            int r = v >> 3, cq = (v & 7) << 3;
            uint32_t dst = bb + (uint32_t)(r * LDS_H + cq) * 2;
            cpa16s(dst, B + (n0 + r) * K + k0 + cq);
        }
    };

    int wm = (wid & 3) * 32;          // 0,32,64,96
    int wn = (wid >> 2) * 64;         // 0,64,128,192
    int g = lane >> 2, tg = lane & 3;

    // ldmatrix per-lane row/col offsets
    int arow = ((lane >> 3) & 1) * 8 + (lane & 7);
    int acol = (lane >> 4) * 8;
    int brow = ((lane >> 4) & 1) * 8 + (lane & 7);
    int bcol = ((lane >> 3) & 1) * 8;

    float acc[2][8][4];
    #pragma unroll
    for (int i = 0; i < 2; i++)
        #pragma unroll
        for (int j = 0; j < 8; j++)
            #pragma unroll
            for (int q = 0; q < 4; q++) acc[i][j][q] = 0.f;

    int nk = K / BK;
    #pragma unroll
    for (int s = 0; s < NST - 1; s++) { loadA(s, s * BK); loadB(s, s * BK); cpa_commit(); }

    for (int kt = 0; kt < nk; kt++) {
        asm volatile("cp.async.wait_group %0;" :: "n"(NST - 2));
        __syncthreads();
        // issue loads for stage kt+NST-1 (overwrites the stage read at kt-1;
        // all warps passed that compute before this sync)
        if (kt + NST - 1 < nk) {
            int s = (kt + NST - 1) % NST;
            loadA(s, (kt + NST - 1) * BK);
            loadB(s, (kt + NST - 1) * BK);
        }
        cpa_commit();

        int st = kt % NST;
        uint32_t abase = sbase + (uint32_t)(st * STG_H) * 2;
        uint32_t bbase = sbase + (uint32_t)(st * STG_H + ATILE) * 2;

        #pragma unroll
        for (int kc = 0; kc < 4; kc++) {
            uint32_t af[2][4];
            #pragma unroll
            for (int i = 0; i < 2; i++)
                ldm_x4(af[i], abase + (uint32_t)((wm + i * 16 + arow) * LDS_H + kc * 16 + acol) * 2);
            #pragma unroll
            for (int p = 0; p < 4; p++) {
                uint32_t bf[4];
                ldm_x4(bf, bbase + (uint32_t)((wn + p * 16 + brow) * LDS_H + kc * 16 + bcol) * 2);
                #pragma unroll
                for (int i = 0; i < 2; i++) {
                    mma16816(acc[i][2 * p],     af[i], bf);
                    mma16816(acc[i][2 * p + 1], af[i], bf + 2);
                }
            }
        }
    }

    // epilogue
    __half* Ch = (__half*)Cv;
    float*  Cf = (float*)Cv;
    auto emit = [&](int r, long long c, float v) {
        if (r < M) {
            if (EPI >= 1) v += bias[c];
            if (EPI == 2) v = 0.5f * v * (1.f + erff(v * 0.70710678118654752f));
            if (EPI == 3) {
                v += res[(long long)r * N + c];
                Cf[(long long)r * N + c] = v;
            } else {
                Ch[(long long)r * N + c] = __float2half_rn(v);
            }
        }
    };
    #pragma unroll
    for (int i = 0; i < 2; i++) {
        int r0 = m0 + wm + i * 16 + g;
        #pragma unroll
        for (int j = 0; j < 8; j++) {
            long long c0 = n0 + wn + j * 8 + 2 * tg;
            emit(r0,     c0,     acc[i][j][0]);
            emit(r0,     c0 + 1, acc[i][j][1]);
            emit(r0 + 8, c0,     acc[i][j][2]);
            emit(r0 + 8, c0 + 1, acc[i][j][3]);
        }
    }
}

// =====================================================================
// flash attention: per (qtile, b*h). 256 threads, 8 warps x 16 q-rows.
// =====================================================================
constexpr int FP = 72;                    // padded halves per row
constexpr int FTILE = 128 * FP;           // halves per tile buffer
constexpr int FSMEM = 5 * FTILE * 2;      // Q + 2K + 2V = 92160 B
constexpr int NQT = (CS + 127) / 128;     // 5

__global__ void __launch_bounds__(256, 1) flash_k(
    const __half* __restrict__ qkv, __half* __restrict__ ctx)
{
    extern __shared__ __align__(16) __half fs[];
    uint32_t sbase = smem_u32(fs);

    int q0 = blockIdx.x * 128;
    int bh = blockIdx.y;
    int b = bh / CH, h = bh % CH;
    int tid = threadIdx.x, lane = tid & 31, wid = tid >> 5;
    int g = lane >> 2, tg = lane & 3;

    const __half* qbase = qkv + (long long)b * CS * (3 * CD) + h * CDH;

    uint32_t sQ = sbase;
    uint32_t sK[2] = { sbase + FTILE * 2u, sbase + FTILE * 4u };
    uint32_t sV[2] = { sbase + FTILE * 6u, sbase + FTILE * 8u };

    auto load_tile = [&](uint32_t dstb, const __half* src, int t0) {
        #pragma unroll
        for (int i = 0; i < 4; i++) {
            int v = tid + i * 256;
            int r = v >> 3, c8 = (v & 7) << 3;
            uint32_t dst = dstb + (uint32_t)(r * FP + c8) * 2;
            if (t0 + r < CS) cpa16s(dst, src + (long long)(t0 + r) * (3 * CD) + c8);
            else             sts_zero16(dst);
        }
    };

    load_tile(sQ, qbase, q0);
    load_tile(sK[0], qbase + CD, 0);
    load_tile(sV[0], qbase + 2 * CD, 0);
    cpa_commit();

    int arow = ((lane >> 3) & 1) * 8 + (lane & 7);
    int acol = (lane >> 4) * 8;
    int brow = ((lane >> 4) & 1) * 8 + (lane & 7);
    int bcol = ((lane >> 3) & 1) * 8;
    int trow = ((lane >> 3) & 1) * 8 + (lane & 7);
    int tcol = (lane >> 4) * 8;

    asm volatile("cp.async.wait_group 0;");
    __syncthreads();

    uint32_t af_q[4][4];
    {
        __half2 sc = __float2half2_rn(0.125f);
        #pragma unroll
        for (int ks = 0; ks < 4; ks++) {
            ldm_x4(af_q[ks], sQ + (uint32_t)((wid * 16 + arow) * FP + ks * 16 + acol) * 2);
            #pragma unroll
            for (int q = 0; q < 4; q++) {
                __half2 v = *(__half2*)&af_q[ks][q];
                v = __hmul2(v, sc);
                af_q[ks][q] = *(uint32_t*)&v;
            }
        }
    }

    float acc_o[8][4];
    #pragma unroll
    for (int j = 0; j < 8; j++)
        #pragma unroll
        for (int q = 0; q < 4; q++) acc_o[j][q] = 0.f;
    float m_lo = -1e30f, m_hi = -1e30f, l_lo = 0.f, l_hi = 0.f;

    for (int t = 0; t < NQT; t++) {
        int buf = t & 1;
        __syncthreads();
        if (t + 1 < NQT) {
            load_tile(sK[buf ^ 1], qbase + CD, (t + 1) * 128);
            load_tile(sV[buf ^ 1], qbase + 2 * CD, (t + 1) * 128);
            cpa_commit();
            asm volatile("cp.async.wait_group 1;");
        } else {
            asm volatile("cp.async.wait_group 0;");
        }
        __syncthreads();

        int valid = CS - t * 128;

        float s[16][4];
        #pragma unroll
        for (int j = 0; j < 16; j++)
            #pragma unroll
            for (int q = 0; q < 4; q++) s[j][q] = 0.f;
        #pragma unroll
        for (int ks = 0; ks < 4; ks++) {
            #pragma unroll
            for (int p = 0; p < 8; p++) {
                uint32_t bf[4];
                ldm_x4(bf, sK[buf] + (uint32_t)((p * 16 + brow) * FP + ks * 16 + bcol) * 2);
                mma16816(s[2 * p],     af_q[ks], bf);
                mma16816(s[2 * p + 1], af_q[ks], bf + 2);
            }
        }

        if (valid < 128) {
            #pragma unroll
            for (int j = 0; j < 16; j++) {
                int c = j * 8 + 2 * tg;
                if (c     >= valid) { s[j][0] = -1e30f; s[j][2] = -1e30f; }
                if (c + 1 >= valid) { s[j][1] = -1e30f; s[j][3] = -1e30f; }
            }
        }

        float mx_lo = -1e30f, mx_hi = -1e30f;
        #pragma unroll
        for (int j = 0; j < 16; j++) {
            mx_lo = fmaxf(mx_lo, fmaxf(s[j][0], s[j][1]));
            mx_hi = fmaxf(mx_hi, fmaxf(s[j][2], s[j][3]));
        }
        mx_lo = fmaxf(mx_lo, __shfl_xor_sync(0xffffffffu, mx_lo, 1));
        mx_lo = fmaxf(mx_lo, __shfl_xor_sync(0xffffffffu, mx_lo, 2));
        mx_hi = fmaxf(mx_hi, __shfl_xor_sync(0xffffffffu, mx_hi, 1));
        mx_hi = fmaxf(mx_hi, __shfl_xor_sync(0xffffffffu, mx_hi, 2));

        float mn_lo = fmaxf(m_lo, mx_lo), mn_hi = fmaxf(m_hi, mx_hi);
        float corr_lo = __expf(m_lo - mn_lo), corr_hi = __expf(m_hi - mn_hi);
        m_lo = mn_lo; m_hi = mn_hi;

        float sum_lo = 0.f, sum_hi = 0.f;
        uint32_t pf[8][4];
        #pragma unroll
        for (int kt = 0; kt < 8; kt++) {
            float p00 = __expf(s[2 * kt][0] - mn_lo);
            float p01 = __expf(s[2 * kt][1] - mn_lo);
            float p02 = __expf(s[2 * kt][2] - mn_hi);
            float p03 = __expf(s[2 * kt][3] - mn_hi);
            float p10 = __expf(s[2 * kt + 1][0] - mn_lo);
            float p11 = __expf(s[2 * kt + 1][1] - mn_lo);
            float p12 = __expf(s[2 * kt + 1][2] - mn_hi);
            float p13 = __expf(s[2 * kt + 1][3] - mn_hi);
            sum_lo += p00 + p01 + p10 + p11;
            sum_hi += p02 + p03 + p12 + p13;
            __half2 h0 = __floats2half2_rn(p00, p01);
            __half2 h1 = __floats2half2_rn(p02, p03);
            __half2 h2 = __floats2half2_rn(p10, p11);
            __half2 h3 = __floats2half2_rn(p12, p13);
            pf[kt][0] = *(uint32_t*)&h0;
            pf[kt][1] = *(uint32_t*)&h1;
            pf[kt][2] = *(uint32_t*)&h2;
            pf[kt][3] = *(uint32_t*)&h3;
        }
        sum_lo += __shfl_xor_sync(0xffffffffu, sum_lo, 1);
        sum_lo += __shfl_xor_sync(0xffffffffu, sum_lo, 2);
        sum_hi += __shfl_xor_sync(0xffffffffu, sum_hi, 1);
        sum_hi += __shfl_xor_sync(0xffffffffu, sum_hi, 2);
        l_lo = l_lo * corr_lo + sum_lo;
        l_hi = l_hi * corr_hi + sum_hi;

        #pragma unroll
        for (int j = 0; j < 8; j++) {
            acc_o[j][0] *= corr_lo; acc_o[j][1] *= corr_lo;
            acc_o[j][2] *= corr_hi; acc_o[j][3] *= corr_hi;
        }

        #pragma unroll
        for (int kt = 0; kt < 8; kt++) {
            #pragma unroll
            for (int ep = 0; ep < 2; ep++) {
                uint32_t bf[4];
                ldm_x4_t(bf, sV[buf] + (uint32_t)((kt * 16 + trow) * FP + ep * 32 + tcol) * 2);
                mma16816(acc_o[4 * ep],     pf[kt], bf);
                mma16816(acc_o[4 * ep + 1], pf[kt], bf + 2);
            }
            #pragma unroll
            for (int ep = 0; ep < 2; ep++) {
                uint32_t bf[4];
                ldm_x4_t(bf, sV[buf] + (uint32_t)((kt * 16 + trow) * FP + ep * 32 + 16 + tcol) * 2);
                mma16816(acc_o[4 * ep + 2], pf[kt], bf);
                mma16816(acc_o[4 * ep + 3], pf[kt], bf + 2);
            }
        }
    }

    float il_lo = 1.f / l_lo, il_hi = 1.f / l_hi;
    int r_lo = q0 + wid * 16 + g;
    int r_hi = r_lo + 8;
    #pragma unroll
    for (int j = 0; j < 8; j++) {
        int c = j * 8 + 2 * tg;
        if (r_lo < CS) {
            __half2 v = __floats2half2_rn(acc_o[j][0] * il_lo, acc_o[j][1] * il_lo);
            *(__half2*)(ctx + (long long)(b * CS + r_lo) * CD + h * CDH + c) = v;
        }
        if (r_hi < CS) {
            __half2 v = __floats2half2_rn(acc_o[j][2] * il_hi, acc_o[j][3] * il_hi);
            *(__half2*)(ctx + (long long)(b * CS + r_hi) * CD + h * CDH + c) = v;
        }
    }
}

// ---------------- launch ----------------
extern "C" void kernel_launch(void* const* d_in, const int* in_sizes, int n_in,
                              void* d_out, int out_size) {
    const float* x    = (const float*)d_in[0];
    const float* ln1w = (const float*)d_in[1];
    const float* ln1b = (const float*)d_in[2];
    const float* Wq   = (const float*)d_in[3];
    const float* bq   = (const float*)d_in[4];
    const float* Wk   = (const float*)d_in[5];
    const float* bk   = (const float*)d_in[6];
    const float* Wv   = (const float*)d_in[7];
    const float* bv   = (const float*)d_in[8];
    const float* Wo   = (const float*)d_in[9];
    const float* bo   = (const float*)d_in[10];
    const float* ln2w = (const float*)d_in[11];
    const float* ln2b = (const float*)d_in[12];
    const float* W1   = (const float*)d_in[13];
    const float* b1   = (const float*)d_in[14];
    const float* W2   = (const float*)d_in[15];
    const float* b2   = (const float*)d_in[16];
    float* out = (float*)d_out;

    __half *p_h, *p_qkv, *p_ctx, *p_ffn, *p_Wqkvt, *p_Wot, *p_W1t, *p_W2t;
    float *p_x2, *p_bqkv;
    cudaGetSymbolAddress((void**)&p_h,     g_h);
    cudaGetSymbolAddress((void**)&p_qkv,   g_qkv);
    cudaGetSymbolAddress((void**)&p_ctx,   g_ctx);
    cudaGetSymbolAddress((void**)&p_x2,    g_x2);
    cudaGetSymbolAddress((void**)&p_ffn,   g_ffn);
    cudaGetSymbolAddress((void**)&p_Wqkvt, g_Wqkvt);
    cudaGetSymbolAddress((void**)&p_bqkv,  g_bqkv);
    cudaGetSymbolAddress((void**)&p_Wot,   g_Wot);
    cudaGetSymbolAddress((void**)&p_W1t,   g_W1t);
    cudaGetSymbolAddress((void**)&p_W2t,   g_W2t);

    cudaFuncSetAttribute(hgemm2<1>, cudaFuncAttributeMaxDynamicSharedMemorySize, DSMEM);
    cudaFuncSetAttribute(hgemm2<2>, cudaFuncAttributeMaxDynamicSharedMemorySize, DSMEM);
    cudaFuncSetAttribute(hgemm2<3>, cudaFuncAttributeMaxDynamicSharedMemorySize, DSMEM);
    cudaFuncSetAttribute(flash_k,   cudaFuncAttributeMaxDynamicSharedMemorySize, FSMEM);

    dim3 tb(32, 8);

    // weight prep (k-major fp16)
    qkv_t_k<<<dim3(CD / 32, 3 * CD / 32), tb>>>(Wq, Wk, Wv);
    bias_pack_k<<<(3 * CD + 255) / 256, 256>>>(bq, bk, bv);
    transpose_h<<<dim3(CD / 32, CD / 32), tb>>>(Wo, p_Wot, CD, CD);
    transpose_h<<<dim3(CFF / 32, CD / 32), tb>>>(W1, p_W1t, CD, CFF);
    transpose_h<<<dim3(CD / 32, CFF / 32), tb>>>(W2, p_W2t, CFF, CD);

    int mtiles = (MALL + BM - 1) / BM;   // 145

    // LN1
    ln_k<<<MALL, 256>>>(x, ln1w, ln1b, p_h);

    // QKV: [18464,768] x [2304,768]^T (+bias) -> fp16
    hgemm2<1><<<dim3(3 * CD / BN, mtiles), NTHR, DSMEM>>>(
        p_h, p_Wqkvt, p_qkv, p_bqkv, nullptr, MALL, 3 * CD, CD);

    // fused attention -> ctx fp16
    flash_k<<<dim3(NQT, CB * CH), 256, FSMEM>>>(p_qkv, p_ctx);

    // x2 = ctx @ Wo + bo + x  (fp32 out)
    hgemm2<3><<<dim3(CD / BN, mtiles), NTHR, DSMEM>>>(
        p_ctx, p_Wot, p_x2, bo, x, MALL, CD, CD);

    // LN2
    ln_k<<<MALL, 256>>>(p_x2, ln2w, ln2b, p_h);

    // ffn = GELU(h2 @ W1 + b1) -> fp16
    hgemm2<2><<<dim3(CFF / BN, mtiles), NTHR, DSMEM>>>(
        p_h, p_W1t, p_ffn, b1, nullptr, MALL, CFF, CD);

    // out = ffn @ W2 + b2 + x2  (fp32 out)
    hgemm2<3><<<dim3(CD / BN, mtiles), NTHR, DSMEM>>>(
        p_ffn, p_W2t, out, b2, p_x2, MALL, CD, CFF);
}

// round 9
// speedup vs baseline: 2.6032x; 1.1862x over previous
#include <cuda_runtime.h>
#include <cuda_fp16.h>
#include <cstdint>
#include <math.h>

#define DEVI __device__ __forceinline__

// ---------------- problem constants ----------------
constexpr int CB = 32, CS = 577, CD = 768, CH = 12, CDH = 64, CFF = 3072;
constexpr int MALL = CB * CS;            // 18464 rows
constexpr float LNEPS = 1e-5f;

// ---------------- device scratch (allocation-free) ----------------
__device__ __half g_h   [MALL * CD];              // LN out (GEMM A)
__device__ __half g_qkv [MALL * 3 * CD];          // q|k|v fp16, row ld = 2304
__device__ __half g_ctx [MALL * CD];              // attention ctx fp16
__device__ float  g_x2  [MALL * CD];              // x + attn_out (fp32 residual)
__device__ __half g_ffn [MALL * CFF];             // GELU out fp16
__device__ __half g_Wqkvt[3 * CD * CD];           // [2304][768] k-major
__device__ float  g_bqkv [3 * CD];
__device__ __half g_Wot  [CD * CD];               // [768][768] k-major
__device__ __half g_W1t  [CFF * CD];              // [3072][768]
__device__ __half g_W2t  [CD * CFF];              // [768][3072]

// ---------------- helpers ----------------
DEVI uint32_t smem_u32(const void* p) {
    uint32_t a;
    asm("{ .reg .u64 t; cvta.to.shared.u64 t, %1; cvt.u32.u64 %0, t; }" : "=r"(a) : "l"(p));
    return a;
}
DEVI void cpa16s(uint32_t dst, const void* g) {
    asm volatile("cp.async.cg.shared.global [%0], [%1], 16;" :: "r"(dst), "l"(g));
}
DEVI void cpa_commit() { asm volatile("cp.async.commit_group;"); }
DEVI void sts_zero16(uint32_t dst) {
    asm volatile("st.shared.v4.b32 [%0], {%1,%1,%1,%1};" :: "r"(dst), "r"(0));
}
DEVI void ldm_x4(uint32_t* r, uint32_t addr) {
    asm volatile("ldmatrix.sync.aligned.m8n8.x4.shared.b16 {%0,%1,%2,%3}, [%4];"
        : "=r"(r[0]), "=r"(r[1]), "=r"(r[2]), "=r"(r[3]) : "r"(addr));
}
DEVI void ldm_x4_t(uint32_t* r, uint32_t addr) {
    asm volatile("ldmatrix.sync.aligned.m8n8.x4.trans.shared.b16 {%0,%1,%2,%3}, [%4];"
        : "=r"(r[0]), "=r"(r[1]), "=r"(r[2]), "=r"(r[3]) : "r"(addr));
}
DEVI void mma16816(float* c, const uint32_t* a, const uint32_t* b) {
    asm volatile(
        "mma.sync.aligned.m16n8k16.row.col.f32.f16.f16.f32 "
        "{%0,%1,%2,%3},{%4,%5,%6,%7},{%8,%9},{%0,%1,%2,%3};"
        : "+f"(c[0]), "+f"(c[1]), "+f"(c[2]), "+f"(c[3])
        : "r"(a[0]), "r"(a[1]), "r"(a[2]), "r"(a[3]), "r"(b[0]), "r"(b[1]));
}

// ---------------- weight prep ----------------
__global__ void transpose_h(const float* __restrict__ src, __half* __restrict__ dst,
                            int R, int C) {
    __shared__ float t[32][33];
    int c0 = blockIdx.x * 32, r0 = blockIdx.y * 32;
    int tx = threadIdx.x, ty = threadIdx.y;
    #pragma unroll
    for (int i = 0; i < 32; i += 8)
        t[ty + i][tx] = src[(long long)(r0 + ty + i) * C + c0 + tx];
    __syncthreads();
    #pragma unroll
    for (int i = 0; i < 32; i += 8)
        dst[(long long)(c0 + ty + i) * R + r0 + tx] = __float2half_rn(t[tx][ty + i]);
}

__global__ void qkv_t_k(const float* __restrict__ Wq, const float* __restrict__ Wk,
                        const float* __restrict__ Wv) {
    __shared__ float t[32][33];
    int n0 = blockIdx.y * 32, k0 = blockIdx.x * 32;
    int which = n0 / CD;
    int c0 = n0 % CD, h = c0 >> 6, e0 = c0 & 63;
    const float* W = (which == 0) ? Wq : (which == 1) ? Wk : Wv;
    const float* base = W + (long long)h * CD * CDH;
    int tx = threadIdx.x, ty = threadIdx.y;
    #pragma unroll
    for (int i = 0; i < 32; i += 8)
        t[ty + i][tx] = base[(long long)(k0 + ty + i) * CDH + e0 + tx];
    __syncthreads();
    #pragma unroll
    for (int i = 0; i < 32; i += 8)
        g_Wqkvt[(long long)(n0 + ty + i) * CD + k0 + tx] = __float2half_rn(t[tx][ty + i]);
}

__global__ void bias_pack_k(const float* __restrict__ bq, const float* __restrict__ bk,
                            const float* __restrict__ bv) {
    int i = blockIdx.x * 256 + threadIdx.x;
    if (i < 3 * CD) {
        int w = i / CD, c = i % CD;
        g_bqkv[i] = ((w == 0) ? bq : (w == 1) ? bk : bv)[c];
    }
}

// ---------------- layer norm: warp-per-row, shfl-only ----------------
__global__ void ln_k(const float* __restrict__ x, const float* __restrict__ w,
                     const float* __restrict__ b, __half* __restrict__ o) {
    int row = blockIdx.x * 8 + (threadIdx.x >> 5);
    int lane = threadIdx.x & 31;
    const float4* xr = (const float4*)(x + (long long)row * CD);
    float4 v[6];
    float s = 0.f;
    #pragma unroll
    for (int i = 0; i < 6; i++) {
        v[i] = xr[lane + 32 * i];
        s += (v[i].x + v[i].y) + (v[i].z + v[i].w);
    }
    #pragma unroll
    for (int t = 16; t > 0; t >>= 1) s += __shfl_xor_sync(0xffffffffu, s, t);
    float mu = s * (1.f / (float)CD);
    float q = 0.f;
    #pragma unroll
    for (int i = 0; i < 6; i++) {
        float dx = v[i].x - mu, dy = v[i].y - mu, dz = v[i].z - mu, dw = v[i].w - mu;
        q += dx * dx + dy * dy + dz * dz + dw * dw;
    }
    #pragma unroll
    for (int t = 16; t > 0; t >>= 1) q += __shfl_xor_sync(0xffffffffu, q, t);
    float rs = rsqrtf(q * (1.f / (float)CD) + LNEPS);
    __half* orow = o + (long long)row * CD;
    #pragma unroll
    for (int i = 0; i < 6; i++) {
        int c = (lane + 32 * i) * 4;
        float4 wv = *(const float4*)(w + c);
        float4 bv = *(const float4*)(b + c);
        __half2 h0 = __floats2half2_rn((v[i].x - mu) * rs * wv.x + bv.x,
                                       (v[i].y - mu) * rs * wv.y + bv.y);
        __half2 h1 = __floats2half2_rn((v[i].z - mu) * rs * wv.z + bv.z,
                                       (v[i].w - mu) * rs * wv.w + bv.w);
        *(__half2*)(orow + c) = h0;
        *(__half2*)(orow + c + 2) = h1;
    }
}

// =====================================================================
// big-tile fp16 GEMM: C[M,N] = A[M,K] * B[N,K]^T (+epilogue)
// 128x256x64, 16 warps x (32x64), ldmatrix fragments, 3-stage cp.async,
// ONE __syncthreads per k-tile (CUTLASS multistage ordering).
// EPI: 1 = +bias, half out; 2 = +bias GELU, half out; 3 = +bias+res, float out
// =====================================================================
constexpr int BM = 128, BN = 256, BK = 64, NST = 3;
constexpr int NTHR = 512;
constexpr int LDS_H = BK + 8;              // 72 halves per row (144 B)
constexpr int ATILE = BM * LDS_H;          // halves
constexpr int BTILE = BN * LDS_H;
constexpr int STG_H = ATILE + BTILE;       // 27648 halves = 55296 B
constexpr int DSMEM = NST * STG_H * 2;     // 165888 B

template <int EPI>
__global__ void __launch_bounds__(NTHR, 1) hgemm2(
    const __half* __restrict__ A, const __half* __restrict__ B, void* __restrict__ Cv,
    const float* __restrict__ bias, const float* __restrict__ res,
    int M, int N, int K)
{
    extern __shared__ __align__(16) __half sh[];
    uint32_t sbase = smem_u32(sh);

    int m0 = blockIdx.y * BM;
    long long n0 = (long long)blockIdx.x * BN;
    int tid = threadIdx.x, lane = tid & 31, wid = tid >> 5;

    auto loadA = [&](int s, int k0) {
        uint32_t ab = sbase + (uint32_t)(s * STG_H) * 2;
        #pragma unroll
        for (int i = 0; i < 2; i++) {
            int v = tid + i * NTHR;
            int r = v >> 3, cq = (v & 7) << 3;
            uint32_t dst = ab + (uint32_t)(r * LDS_H + cq) * 2;
            int gm = m0 + r;
            if (gm < M) cpa16s(dst, A + (long long)gm * K + k0 + cq);
            else        sts_zero16(dst);
        }
    };
    auto loadB = [&](int s, int k0) {
        uint32_t bb = sbase + (uint32_t)(s * STG_H + ATILE) * 2;
        #pragma unroll
        for (int i = 0; i < 4; i++) {
            int v = tid + i * NTHR;
            int r = v >> 3, cq = (v & 7) << 3;
            uint32_t dst = bb + (uint32_t)(r * LDS_H + cq) * 2;
            cpa16s(dst, B + (n0 + r) * K + k0 + cq);
        }
    };

    int wm = (wid & 3) * 32;          // 0,32,64,96
    int wn = (wid >> 2) * 64;         // 0,64,128,192
    int g = lane >> 2, tg = lane & 3;

    // ldmatrix per-lane row/col offsets
    int arow = ((lane >> 3) & 1) * 8 + (lane & 7);
    int acol = (lane >> 4) * 8;
    int brow = ((lane >> 4) & 1) * 8 + (lane & 7);
    int bcol = ((lane >> 3) & 1) * 8;

    float acc[2][8][4];
    #pragma unroll
    for (int i = 0; i < 2; i++)
        #pragma unroll
        for (int j = 0; j < 8; j++)
            #pragma unroll
            for (int q = 0; q < 4; q++) acc[i][j][q] = 0.f;

    int nk = K / BK;
    #pragma unroll
    for (int s = 0; s < NST - 1; s++) { loadA(s, s * BK); loadB(s, s * BK); cpa_commit(); }

    for (int kt = 0; kt < nk; kt++) {
        asm volatile("cp.async.wait_group %0;" :: "n"(NST - 2));
        __syncthreads();
        // issue loads for stage kt+NST-1 (overwrites the stage read at kt-1;
        // all warps passed that compute before this sync)
        if (kt + NST - 1 < nk) {
            int s = (kt + NST - 1) % NST;
            loadA(s, (kt + NST - 1) * BK);
            loadB(s, (kt + NST - 1) * BK);
        }
        cpa_commit();

        int st = kt % NST;
        uint32_t abase = sbase + (uint32_t)(st * STG_H) * 2;
        uint32_t bbase = sbase + (uint32_t)(st * STG_H + ATILE) * 2;

        #pragma unroll
        for (int kc = 0; kc < 4; kc++) {
            uint32_t af[2][4];
            #pragma unroll
            for (int i = 0; i < 2; i++)
                ldm_x4(af[i], abase + (uint32_t)((wm + i * 16 + arow) * LDS_H + kc * 16 + acol) * 2);
            #pragma unroll
            for (int p = 0; p < 4; p++) {
                uint32_t bf[4];
                ldm_x4(bf, bbase + (uint32_t)((wn + p * 16 + brow) * LDS_H + kc * 16 + bcol) * 2);
                #pragma unroll
                for (int i = 0; i < 2; i++) {
                    mma16816(acc[i][2 * p],     af[i], bf);
                    mma16816(acc[i][2 * p + 1], af[i], bf + 2);
                }
            }
        }
    }

    // epilogue (vectorized: half2 / float2 per accumulator pair)
    __half* Ch = (__half*)Cv;
    float*  Cf = (float*)Cv;
    auto emit2 = [&](int r, long long c, float v0, float v1) {
        if (r < M) {
            if (EPI >= 1) {
                float2 b2 = *(const float2*)(bias + c);
                v0 += b2.x; v1 += b2.y;
            }
            if (EPI == 2) {
                v0 = 0.5f * v0 * (1.f + erff(v0 * 0.70710678118654752f));
                v1 = 0.5f * v1 * (1.f + erff(v1 * 0.70710678118654752f));
            }
            if (EPI == 3) {
                float2 r2 = *(const float2*)(res + (long long)r * N + c);
                v0 += r2.x; v1 += r2.y;
                *(float2*)(Cf + (long long)r * N + c) = make_float2(v0, v1);
            } else {
                *(__half2*)(Ch + (long long)r * N + c) = __floats2half2_rn(v0, v1);
            }
        }
    };
    #pragma unroll
    for (int i = 0; i < 2; i++) {
        int r0 = m0 + wm + i * 16 + g;
        #pragma unroll
        for (int j = 0; j < 8; j++) {
            long long c0 = n0 + wn + j * 8 + 2 * tg;
            emit2(r0,     c0, acc[i][j][0], acc[i][j][1]);
            emit2(r0 + 8, c0, acc[i][j][2], acc[i][j][3]);
        }
    }
}

// =====================================================================
// flash attention: per (qtile, b*h). 256 threads, 8 warps x 16 q-rows.
// =====================================================================
constexpr int FP = 72;                    // padded halves per row
constexpr int FTILE = 128 * FP;           // halves per tile buffer
constexpr int FSMEM = 5 * FTILE * 2;      // Q + 2K + 2V = 92160 B
constexpr int NQT = (CS + 127) / 128;     // 5

__global__ void __launch_bounds__(256, 1) flash_k(
    const __half* __restrict__ qkv, __half* __restrict__ ctx)
{
    extern __shared__ __align__(16) __half fs[];
    uint32_t sbase = smem_u32(fs);

    int q0 = blockIdx.x * 128;
    int bh = blockIdx.y;
    int b = bh / CH, h = bh % CH;
    int tid = threadIdx.x, lane = tid & 31, wid = tid >> 5;
    int g = lane >> 2, tg = lane & 3;

    const __half* qbase = qkv + (long long)b * CS * (3 * CD) + h * CDH;

    uint32_t sQ = sbase;
    uint32_t sK[2] = { sbase + FTILE * 2u, sbase + FTILE * 4u };
    uint32_t sV[2] = { sbase + FTILE * 6u, sbase + FTILE * 8u };

    auto load_tile = [&](uint32_t dstb, const __half* src, int t0) {
        #pragma unroll
        for (int i = 0; i < 4; i++) {
            int v = tid + i * 256;
            int r = v >> 3, c8 = (v & 7) << 3;
            uint32_t dst = dstb + (uint32_t)(r * FP + c8) * 2;
            if (t0 + r < CS) cpa16s(dst, src + (long long)(t0 + r) * (3 * CD) + c8);
            else             sts_zero16(dst);
        }
    };

    load_tile(sQ, qbase, q0);
    load_tile(sK[0], qbase + CD, 0);
    load_tile(sV[0], qbase + 2 * CD, 0);
    cpa_commit();

    int arow = ((lane >> 3) & 1) * 8 + (lane & 7);
    int acol = (lane >> 4) * 8;
    int brow = ((lane >> 4) & 1) * 8 + (lane & 7);
    int bcol = ((lane >> 3) & 1) * 8;
    int trow = ((lane >> 3) & 1) * 8 + (lane & 7);
    int tcol = (lane >> 4) * 8;

    asm volatile("cp.async.wait_group 0;");
    __syncthreads();

    uint32_t af_q[4][4];
    {
        __half2 sc = __float2half2_rn(0.125f);
        #pragma unroll
        for (int ks = 0; ks < 4; ks++) {
            ldm_x4(af_q[ks], sQ + (uint32_t)((wid * 16 + arow) * FP + ks * 16 + acol) * 2);
            #pragma unroll
            for (int q = 0; q < 4; q++) {
                __half2 v = *(__half2*)&af_q[ks][q];
                v = __hmul2(v, sc);
                af_q[ks][q] = *(uint32_t*)&v;
            }
        }
    }

    float acc_o[8][4];
    #pragma unroll
    for (int j = 0; j < 8; j++)
        #pragma unroll
        for (int q = 0; q < 4; q++) acc_o[j][q] = 0.f;
    float m_lo = -1e30f, m_hi = -1e30f, l_lo = 0.f, l_hi = 0.f;

    for (int t = 0; t < NQT; t++) {
        int buf = t & 1;
        __syncthreads();
        if (t + 1 < NQT) {
            load_tile(sK[buf ^ 1], qbase + CD, (t + 1) * 128);
            load_tile(sV[buf ^ 1], qbase + 2 * CD, (t + 1) * 128);
            cpa_commit();
            asm volatile("cp.async.wait_group 1;");
        } else {
            asm volatile("cp.async.wait_group 0;");
        }
        __syncthreads();

        int valid = CS - t * 128;

        float s[16][4];
        #pragma unroll
        for (int j = 0; j < 16; j++)
            #pragma unroll
            for (int q = 0; q < 4; q++) s[j][q] = 0.f;
        #pragma unroll
        for (int ks = 0; ks < 4; ks++) {
            #pragma unroll
            for (int p = 0; p < 8; p++) {
                uint32_t bf[4];
                ldm_x4(bf, sK[buf] + (uint32_t)((p * 16 + brow) * FP + ks * 16 + bcol) * 2);
                mma16816(s[2 * p],     af_q[ks], bf);
                mma16816(s[2 * p + 1], af_q[ks], bf + 2);
            }
        }

        if (valid < 128) {
            #pragma unroll
            for (int j = 0; j < 16; j++) {
                int c = j * 8 + 2 * tg;
                if (c     >= valid) { s[j][0] = -1e30f; s[j][2] = -1e30f; }
                if (c + 1 >= valid) { s[j][1] = -1e30f; s[j][3] = -1e30f; }
            }
        }

        float mx_lo = -1e30f, mx_hi = -1e30f;
        #pragma unroll
        for (int j = 0; j < 16; j++) {
            mx_lo = fmaxf(mx_lo, fmaxf(s[j][0], s[j][1]));
            mx_hi = fmaxf(mx_hi, fmaxf(s[j][2], s[j][3]));
        }
        mx_lo = fmaxf(mx_lo, __shfl_xor_sync(0xffffffffu, mx_lo, 1));
        mx_lo = fmaxf(mx_lo, __shfl_xor_sync(0xffffffffu, mx_lo, 2));
        mx_hi = fmaxf(mx_hi, __shfl_xor_sync(0xffffffffu, mx_hi, 1));
        mx_hi = fmaxf(mx_hi, __shfl_xor_sync(0xffffffffu, mx_hi, 2));

        float mn_lo = fmaxf(m_lo, mx_lo), mn_hi = fmaxf(m_hi, mx_hi);
        float corr_lo = __expf(m_lo - mn_lo), corr_hi = __expf(m_hi - mn_hi);
        m_lo = mn_lo; m_hi = mn_hi;

        float sum_lo = 0.f, sum_hi = 0.f;
        uint32_t pf[8][4];
        #pragma unroll
        for (int kt = 0; kt < 8; kt++) {
            float p00 = __expf(s[2 * kt][0] - mn_lo);
            float p01 = __expf(s[2 * kt][1] - mn_lo);
            float p02 = __expf(s[2 * kt][2] - mn_hi);
            float p03 = __expf(s[2 * kt][3] - mn_hi);
            float p10 = __expf(s[2 * kt + 1][0] - mn_lo);
            float p11 = __expf(s[2 * kt + 1][1] - mn_lo);
            float p12 = __expf(s[2 * kt + 1][2] - mn_hi);
            float p13 = __expf(s[2 * kt + 1][3] - mn_hi);
            sum_lo += p00 + p01 + p10 + p11;
            sum_hi += p02 + p03 + p12 + p13;
            __half2 h0 = __floats2half2_rn(p00, p01);
            __half2 h1 = __floats2half2_rn(p02, p03);
            __half2 h2 = __floats2half2_rn(p10, p11);
            __half2 h3 = __floats2half2_rn(p12, p13);
            pf[kt][0] = *(uint32_t*)&h0;
            pf[kt][1] = *(uint32_t*)&h1;
            pf[kt][2] = *(uint32_t*)&h2;
            pf[kt][3] = *(uint32_t*)&h3;
        }
        sum_lo += __shfl_xor_sync(0xffffffffu, sum_lo, 1);
        sum_lo += __shfl_xor_sync(0xffffffffu, sum_lo, 2);
        sum_hi += __shfl_xor_sync(0xffffffffu, sum_hi, 1);
        sum_hi += __shfl_xor_sync(0xffffffffu, sum_hi, 2);
        l_lo = l_lo * corr_lo + sum_lo;
        l_hi = l_hi * corr_hi + sum_hi;

        #pragma unroll
        for (int j = 0; j < 8; j++) {
            acc_o[j][0] *= corr_lo; acc_o[j][1] *= corr_lo;
            acc_o[j][2] *= corr_hi; acc_o[j][3] *= corr_hi;
        }

        #pragma unroll
        for (int kt = 0; kt < 8; kt++) {
            #pragma unroll
            for (int ep = 0; ep < 2; ep++) {
                uint32_t bf[4];
                ldm_x4_t(bf, sV[buf] + (uint32_t)((kt * 16 + trow) * FP + ep * 32 + tcol) * 2);
                mma16816(acc_o[4 * ep],     pf[kt], bf);
                mma16816(acc_o[4 * ep + 1], pf[kt], bf + 2);
            }
            #pragma unroll
            for (int ep = 0; ep < 2; ep++) {
                uint32_t bf[4];
                ldm_x4_t(bf, sV[buf] + (uint32_t)((kt * 16 + trow) * FP + ep * 32 + 16 + tcol) * 2);
                mma16816(acc_o[4 * ep + 2], pf[kt], bf);
                mma16816(acc_o[4 * ep + 3], pf[kt], bf + 2);
            }
        }
    }

    float il_lo = 1.f / l_lo, il_hi = 1.f / l_hi;
    int r_lo = q0 + wid * 16 + g;
    int r_hi = r_lo + 8;
    #pragma unroll
    for (int j = 0; j < 8; j++) {
        int c = j * 8 + 2 * tg;
        if (r_lo < CS) {
            __half2 v = __floats2half2_rn(acc_o[j][0] * il_lo, acc_o[j][1] * il_lo);
            *(__half2*)(ctx + (long long)(b * CS + r_lo) * CD + h * CDH + c) = v;
        }
        if (r_hi < CS) {
            __half2 v = __floats2half2_rn(acc_o[j][2] * il_hi, acc_o[j][3] * il_hi);
            *(__half2*)(ctx + (long long)(b * CS + r_hi) * CD + h * CDH + c) = v;
        }
    }
}

// ---------------- launch ----------------
extern "C" void kernel_launch(void* const* d_in, const int* in_sizes, int n_in,
                              void* d_out, int out_size) {
    const float* x    = (const float*)d_in[0];
    const float* ln1w = (const float*)d_in[1];
    const float* ln1b = (const float*)d_in[2];
    const float* Wq   = (const float*)d_in[3];
    const float* bq   = (const float*)d_in[4];
    const float* Wk   = (const float*)d_in[5];
    const float* bk   = (const float*)d_in[6];
    const float* Wv   = (const float*)d_in[7];
    const float* bv   = (const float*)d_in[8];
    const float* Wo   = (const float*)d_in[9];
    const float* bo   = (const float*)d_in[10];
    const float* ln2w = (const float*)d_in[11];
    const float* ln2b = (const float*)d_in[12];
    const float* W1   = (const float*)d_in[13];
    const float* b1   = (const float*)d_in[14];
    const float* W2   = (const float*)d_in[15];
    const float* b2   = (const float*)d_in[16];
    float* out = (float*)d_out;

    __half *p_h, *p_qkv, *p_ctx, *p_ffn, *p_Wqkvt, *p_Wot, *p_W1t, *p_W2t;
    float *p_x2, *p_bqkv;
    cudaGetSymbolAddress((void**)&p_h,     g_h);
    cudaGetSymbolAddress((void**)&p_qkv,   g_qkv);
    cudaGetSymbolAddress((void**)&p_ctx,   g_ctx);
    cudaGetSymbolAddress((void**)&p_x2,    g_x2);
    cudaGetSymbolAddress((void**)&p_ffn,   g_ffn);
    cudaGetSymbolAddress((void**)&p_Wqkvt, g_Wqkvt);
    cudaGetSymbolAddress((void**)&p_bqkv,  g_bqkv);
    cudaGetSymbolAddress((void**)&p_Wot,   g_Wot);
    cudaGetSymbolAddress((void**)&p_W1t,   g_W1t);
    cudaGetSymbolAddress((void**)&p_W2t,   g_W2t);

    cudaFuncSetAttribute(hgemm2<1>, cudaFuncAttributeMaxDynamicSharedMemorySize, DSMEM);
    cudaFuncSetAttribute(hgemm2<2>, cudaFuncAttributeMaxDynamicSharedMemorySize, DSMEM);
    cudaFuncSetAttribute(hgemm2<3>, cudaFuncAttributeMaxDynamicSharedMemorySize, DSMEM);
    cudaFuncSetAttribute(flash_k,   cudaFuncAttributeMaxDynamicSharedMemorySize, FSMEM);

    dim3 tb(32, 8);

    // weight prep (k-major fp16)
    qkv_t_k<<<dim3(CD / 32, 3 * CD / 32), tb>>>(Wq, Wk, Wv);
    bias_pack_k<<<(3 * CD + 255) / 256, 256>>>(bq, bk, bv);
    transpose_h<<<dim3(CD / 32, CD / 32), tb>>>(Wo, p_Wot, CD, CD);
    transpose_h<<<dim3(CFF / 32, CD / 32), tb>>>(W1, p_W1t, CD, CFF);
    transpose_h<<<dim3(CD / 32, CFF / 32), tb>>>(W2, p_W2t, CFF, CD);

    int mtiles = (MALL + BM - 1) / BM;   // 145

    // LN1 (warp-per-row)
    ln_k<<<MALL / 8, 256>>>(x, ln1w, ln1b, p_h);

    // QKV: [18464,768] x [2304,768]^T (+bias) -> fp16
    hgemm2<1><<<dim3(3 * CD / BN, mtiles), NTHR, DSMEM>>>(
        p_h, p_Wqkvt, p_qkv, p_bqkv, nullptr, MALL, 3 * CD, CD);

    // fused attention -> ctx fp16
    flash_k<<<dim3(NQT, CB * CH), 256, FSMEM>>>(p_qkv, p_ctx);

    // x2 = ctx @ Wo + bo + x  (fp32 out)
    hgemm2<3><<<dim3(CD / BN, mtiles), NTHR, DSMEM>>>(
        p_ctx, p_Wot, p_x2, bo, x, MALL, CD, CD);

    // LN2 (warp-per-row)
    ln_k<<<MALL / 8, 256>>>(p_x2, ln2w, ln2b, p_h);

    // ffn = GELU(h2 @ W1 + b1) -> fp16
    hgemm2<2><<<dim3(CFF / BN, mtiles), NTHR, DSMEM>>>(
        p_h, p_W1t, p_ffn, b1, nullptr, MALL, CFF, CD);

    // out = ffn @ W2 + b2 + x2  (fp32 out)
    hgemm2<3><<<dim3(CD / BN, mtiles), NTHR, DSMEM>>>(
        p_ffn, p_W2t, out, b2, p_x2, MALL, CD, CFF);
}